// round 5
// baseline (speedup 1.0000x reference)
#include <cuda_runtime.h>
#include <cstddef>

// ---------------------------------------------------------------------------
// RelAttnBlock: LN -> QKV proj -> rel-pos attention (QEr fused) -> O proj
// B=8, L=1024, EMB=512, H=8, HD=64, BS=1024
// ---------------------------------------------------------------------------

#define Bq 8
#define Lq 1024
#define EMB 512
#define Hh 8
#define HD 64
#define BSz 1024
#define ROWS (Bq * Lq)          // 8192

// Scratch layout (floats): 5 buffers of ROWS*EMB = 4M floats each (80 MB total)
#define OFF_H    ((size_t)0)
#define OFF_Q    (OFF_H + (size_t)ROWS * EMB)
#define OFF_K    (OFF_Q + (size_t)ROWS * EMB)
#define OFF_V    (OFF_K + (size_t)ROWS * EMB)
#define OFF_CTX  (OFF_V + (size_t)ROWS * EMB)
#define SCRATCH_FLOATS (OFF_CTX + (size_t)ROWS * EMB)

__device__ float g_scratch[SCRATCH_FLOATS];

// ---------------------------------------------------------------------------
// LayerNorm: one block per row, 128 threads, float4 per thread
// ---------------------------------------------------------------------------
__global__ void ln_kernel(const float* __restrict__ x,
                          const float* __restrict__ gamma,
                          const float* __restrict__ beta,
                          float* __restrict__ hout)
{
    __shared__ float wsum[4], wsq[4];
    int row = blockIdx.x;
    int tid = threadIdx.x;
    const float4 v = *(const float4*)(x + (size_t)row * EMB + tid * 4);

    float s  = v.x + v.y + v.z + v.w;
    float sq = v.x * v.x + v.y * v.y + v.z * v.z + v.w * v.w;
    #pragma unroll
    for (int off = 16; off > 0; off >>= 1) {
        s  += __shfl_xor_sync(0xffffffffu, s,  off);
        sq += __shfl_xor_sync(0xffffffffu, sq, off);
    }
    int warp = tid >> 5;
    if ((tid & 31) == 0) { wsum[warp] = s; wsq[warp] = sq; }
    __syncthreads();
    float S  = wsum[0] + wsum[1] + wsum[2] + wsum[3];
    float SQ = wsq[0] + wsq[1] + wsq[2] + wsq[3];

    float mu  = S * (1.0f / EMB);
    float var = SQ * (1.0f / EMB) - mu * mu;
    float rinv = rsqrtf(var + 1e-5f);

    int c = tid * 4;
    float4 o;
    o.x = (v.x - mu) * rinv * gamma[c + 0] + beta[c + 0];
    o.y = (v.y - mu) * rinv * gamma[c + 1] + beta[c + 1];
    o.z = (v.z - mu) * rinv * gamma[c + 2] + beta[c + 2];
    o.w = (v.w - mu) * rinv * gamma[c + 3] + beta[c + 3];
    *(float4*)(hout + (size_t)row * EMB + c) = o;
}

// ---------------------------------------------------------------------------
// Generic SGEMM: C[M,N] = A[M,K] * B[K,N] + bias
// BM=BN=128, BK=8, 256 threads, 8x8 per thread. M%128==0, N%128==0, K%8==0.
// ---------------------------------------------------------------------------
__global__ void sgemm_kernel(int M, int N, int K,
                             const float* __restrict__ A, int lda,
                             const float* __restrict__ B, int ldb,
                             float* __restrict__ C, int ldc,
                             const float* __restrict__ bias)
{
    __shared__ float As[8][128];
    __shared__ float Bs[8][128];

    int bm = blockIdx.y, bn = blockIdx.x;
    int tid = threadIdx.x;
    int ty = tid >> 4, tx = tid & 15;

    const float* Ab = A + (size_t)bm * 128 * lda;
    const float* Bb = B + bn * 128;

    int arow = tid >> 1, acol = (tid & 1) * 4;
    int brow = tid >> 5, bcol = (tid & 31) * 4;

    float acc[8][8];
    #pragma unroll
    for (int i = 0; i < 8; i++)
        #pragma unroll
        for (int j = 0; j < 8; j++) acc[i][j] = 0.0f;

    for (int k0 = 0; k0 < K; k0 += 8) {
        float4 av = *(const float4*)(Ab + (size_t)arow * lda + k0 + acol);
        As[acol + 0][arow] = av.x;
        As[acol + 1][arow] = av.y;
        As[acol + 2][arow] = av.z;
        As[acol + 3][arow] = av.w;
        float4 bv = *(const float4*)(Bb + (size_t)(k0 + brow) * ldb + bcol);
        *(float4*)(&Bs[brow][bcol]) = bv;
        __syncthreads();

        #pragma unroll
        for (int k = 0; k < 8; k++) {
            float a[8], b[8];
            *(float4*)(a)     = *(const float4*)(&As[k][ty * 8]);
            *(float4*)(a + 4) = *(const float4*)(&As[k][ty * 8 + 4]);
            *(float4*)(b)     = *(const float4*)(&Bs[k][tx * 8]);
            *(float4*)(b + 4) = *(const float4*)(&Bs[k][tx * 8 + 4]);
            #pragma unroll
            for (int i = 0; i < 8; i++)
                #pragma unroll
                for (int j = 0; j < 8; j++)
                    acc[i][j] += a[i] * b[j];
        }
        __syncthreads();
    }

    #pragma unroll
    for (int i = 0; i < 8; i++) {
        int row = bm * 128 + ty * 8 + i;
        #pragma unroll
        for (int j = 0; j < 8; j += 4) {
            int col = bn * 128 + tx * 8 + j;
            float4 o;
            o.x = acc[i][j + 0] + (bias ? bias[col + 0] : 0.0f);
            o.y = acc[i][j + 1] + (bias ? bias[col + 1] : 0.0f);
            o.z = acc[i][j + 2] + (bias ? bias[col + 2] : 0.0f);
            o.w = acc[i][j + 3] + (bias ? bias[col + 3] : 0.0f);
            *(float4*)(C + (size_t)row * ldc + col) = o;
        }
    }
}

// ---------------------------------------------------------------------------
// Fused attention with inline relative bias.
// Per (b,h), 32 query rows per block, 256 threads.
// For key tile kt and query block l0: rel index (j - l) mod 1024 spans the
// contiguous (mod) range starting at base = kt*64 - l0 - 31, local index
// li = j - rb - r + 31 in [0, 94]. Load that 95-row Er slab per tile and
// fuse QEr into the score computation.
// smem: qs[32*64] | sc[32*1024] | kv[64*68] | er[95*68]
// ---------------------------------------------------------------------------
#define ERS 95
#define ATTN_SMEM_FLOATS (32 * 64 + 32 * 1024 + 64 * 68 + ERS * 68)
#define ATTN_SMEM_BYTES  (ATTN_SMEM_FLOATS * 4)

__global__ void attn_kernel(const float* __restrict__ gq,
                            const float* __restrict__ gk,
                            const float* __restrict__ gv,
                            const float* __restrict__ ger,
                            float* __restrict__ gctx)
{
    extern __shared__ float sm[];
    float* qs = sm;                                  // [32][64]
    float* sc = sm + 32 * 64;                        // [32][1024]
    float* kv = sm + 32 * 64 + 32 * 1024;            // [64][68]
    float* er = sm + 32 * 64 + 32 * 1024 + 64 * 68;  // [95][68]

    int bh = blockIdx.y;
    int hh = bh & 7;
    int bb = bh >> 3;
    int l0 = blockIdx.x * 32;
    int tid = threadIdx.x;

    // load q tile
    for (int e = tid; e < 32 * 64; e += 256) {
        int i = e >> 6, d = e & 63;
        qs[e] = gq[((size_t)bb * Lq + l0 + i) * EMB + hh * HD + d];
    }
    __syncthreads();

    int j  = tid & 63;
    int rb = (tid >> 6) * 8;

    const float* er_h = ger + (size_t)hh * BSz * HD;   // Er[h] : (BS, HD)

    // ---- Phase 1: scores + fused rel-bias ----
    for (int kt = 0; kt < 16; kt++) {
        // K tile: 64 rows x 64 d
        for (int e = tid; e < 64 * 64; e += 256) {
            int jj = e >> 6, dd = e & 63;
            kv[jj * 68 + dd] = gk[((size_t)bb * Lq + kt * 64 + jj) * EMB + hh * HD + dd];
        }
        // Er slab: 95 rows x 64 d, rows (base + li) mod 1024
        int base = kt * 64 - l0 - 31;   // may be negative; mask handles wrap
        for (int e = tid; e < ERS * 64; e += 256) {
            int li = e >> 6, dd = e & 63;
            int rrow = (base + li) & (BSz - 1);
            er[li * 68 + dd] = er_h[(size_t)rrow * HD + dd];
        }
        __syncthreads();

        float acc[8], eacc[8];
        #pragma unroll
        for (int r = 0; r < 8; r++) { acc[r] = 0.0f; eacc[r] = 0.0f; }

        const float4* kp = (const float4*)(kv + j * 68);
        // per-row Er slab row: li = j - rb - r + 31
        #pragma unroll 2
        for (int d4 = 0; d4 < 16; d4++) {
            float4 kk = kp[d4];
            #pragma unroll
            for (int r = 0; r < 8; r++) {
                float4 qq = *(const float4*)(qs + (rb + r) * 64 + d4 * 4);
                float4 ee = *(const float4*)(er + (j - rb - r + 31) * 68 + d4 * 4);
                acc[r]  += kk.x * qq.x + kk.y * qq.y + kk.z * qq.z + kk.w * qq.w;
                eacc[r] += ee.x * qq.x + ee.y * qq.y + ee.z * qq.z + ee.w * qq.w;
            }
        }
        int gcol = kt * 64 + j;
        #pragma unroll
        for (int r = 0; r < 8; r++)
            sc[(rb + r) * 1024 + gcol] = acc[r] * 0.125f + eacc[r];
        __syncthreads();
    }

    // ---- Phase 2: softmax over 1024 per row; 8 lanes per row ----
    {
        int warp = tid >> 5, lane = tid & 31;
        int row = warp * 4 + (lane >> 3);
        int sub = lane & 7;
        float* srow = sc + row * 1024;

        float m = -1e30f;
        for (int t = 0; t < 128; t++)
            m = fmaxf(m, srow[sub + t * 8]);
        #pragma unroll
        for (int off = 4; off > 0; off >>= 1)
            m = fmaxf(m, __shfl_xor_sync(0xffffffffu, m, off));

        float ssum = 0.0f;
        for (int t = 0; t < 128; t++) {
            float e = __expf(srow[sub + t * 8] - m);
            srow[sub + t * 8] = e;
            ssum += e;
        }
        #pragma unroll
        for (int off = 4; off > 0; off >>= 1)
            ssum += __shfl_xor_sync(0xffffffffu, ssum, off);

        float inv = 1.0f / ssum;
        for (int t = 0; t < 128; t++)
            srow[sub + t * 8] *= inv;
    }
    __syncthreads();

    // ---- Phase 3: out = w @ v ----
    int d = tid & 63;
    float oacc[8];
    #pragma unroll
    for (int r = 0; r < 8; r++) oacc[r] = 0.0f;

    for (int kt = 0; kt < 16; kt++) {
        for (int e = tid; e < 64 * 64; e += 256) {
            int jj = e >> 6, dd = e & 63;
            kv[jj * 68 + dd] = gv[((size_t)bb * Lq + kt * 64 + jj) * EMB + hh * HD + dd];
        }
        __syncthreads();

        #pragma unroll 2
        for (int k4 = 0; k4 < 16; k4++) {
            float v0 = kv[(k4 * 4 + 0) * 68 + d];
            float v1 = kv[(k4 * 4 + 1) * 68 + d];
            float v2 = kv[(k4 * 4 + 2) * 68 + d];
            float v3 = kv[(k4 * 4 + 3) * 68 + d];
            #pragma unroll
            for (int r = 0; r < 8; r++) {
                float4 ss = *(const float4*)(sc + (rb + r) * 1024 + kt * 64 + k4 * 4);
                oacc[r] += ss.x * v0 + ss.y * v1 + ss.z * v2 + ss.w * v3;
            }
        }
        __syncthreads();
    }

    #pragma unroll
    for (int r = 0; r < 8; r++)
        gctx[((size_t)bb * Lq + l0 + rb + r) * EMB + hh * HD + d] = oacc[r];
}

// ---------------------------------------------------------------------------
extern "C" void kernel_launch(void* const* d_in, const int* in_sizes, int n_in,
                              void* d_out, int out_size)
{
    const float* x    = (const float*)d_in[0];
    const float* ln_g = (const float*)d_in[1];
    const float* ln_b = (const float*)d_in[2];
    const float* Wq   = (const float*)d_in[3];
    const float* bq   = (const float*)d_in[4];
    const float* Wk   = (const float*)d_in[5];
    const float* bk   = (const float*)d_in[6];
    const float* Wv   = (const float*)d_in[7];
    const float* bv   = (const float*)d_in[8];
    const float* Wo   = (const float*)d_in[9];
    const float* bo   = (const float*)d_in[10];
    const float* Er   = (const float*)d_in[11];
    float* out = (float*)d_out;

    float* scr = nullptr;
    cudaGetSymbolAddress((void**)&scr, g_scratch);
    float* g_h   = scr + OFF_H;
    float* g_q   = scr + OFF_Q;
    float* g_k   = scr + OFF_K;
    float* g_v   = scr + OFF_V;
    float* g_ctx = scr + OFF_CTX;

    // 1. LayerNorm
    ln_kernel<<<ROWS, 128>>>(x, ln_g, ln_b, g_h);

    // 2. QKV projections
    dim3 gProj(EMB / 128, ROWS / 128);  // (4, 64)
    sgemm_kernel<<<gProj, 256>>>(ROWS, EMB, EMB, g_h, EMB, Wq, EMB, g_q, EMB, bq);
    sgemm_kernel<<<gProj, 256>>>(ROWS, EMB, EMB, g_h, EMB, Wk, EMB, g_k, EMB, bk);
    sgemm_kernel<<<gProj, 256>>>(ROWS, EMB, EMB, g_h, EMB, Wv, EMB, g_v, EMB, bv);

    // 3. Fused attention (scores + rel bias + softmax + w@v)
    static bool attn_attr_set = false;
    if (!attn_attr_set) {
        cudaFuncSetAttribute(attn_kernel, cudaFuncAttributeMaxDynamicSharedMemorySize,
                             ATTN_SMEM_BYTES);
        attn_attr_set = true;
    }
    attn_kernel<<<dim3(Lq / 32, Bq * Hh), 256, ATTN_SMEM_BYTES>>>(g_q, g_k, g_v, Er, g_ctx);

    // 4. Output projection
    sgemm_kernel<<<gProj, 256>>>(ROWS, EMB, EMB, g_ctx, EMB, Wo, EMB, out, EMB, bo);
}

// round 6
// speedup vs baseline: 1.1755x; 1.1755x over previous
#include <cuda_runtime.h>
#include <cstddef>

// ---------------------------------------------------------------------------
// RelAttnBlock: LN -> QKV proj -> rel-pos attention (QEr fused) -> O proj
// B=8, L=1024, EMB=512, H=8, HD=64, BS=1024
// ---------------------------------------------------------------------------

#define Bq 8
#define Lq 1024
#define EMB 512
#define Hh 8
#define HD 64
#define BSz 1024
#define ROWS (Bq * Lq)          // 8192

// Scratch (floats): h,q,k,v,ctx (4M each) + kT (4M) + erT (512K)
#define OFF_H    ((size_t)0)
#define OFF_Q    (OFF_H   + (size_t)ROWS * EMB)
#define OFF_K    (OFF_Q   + (size_t)ROWS * EMB)
#define OFF_V    (OFF_K   + (size_t)ROWS * EMB)
#define OFF_CTX  (OFF_V   + (size_t)ROWS * EMB)
#define OFF_KT   (OFF_CTX + (size_t)ROWS * EMB)              // (B*H, HD, L)
#define OFF_ERT  (OFF_KT  + (size_t)Bq * Hh * HD * Lq)       // (H, HD, BS)
#define SCRATCH_FLOATS (OFF_ERT + (size_t)Hh * HD * BSz)

__device__ float g_scratch[SCRATCH_FLOATS];

// ---------------------------------------------------------------------------
// LayerNorm: one block per row, 128 threads, float4 per thread
// ---------------------------------------------------------------------------
__global__ void ln_kernel(const float* __restrict__ x,
                          const float* __restrict__ gamma,
                          const float* __restrict__ beta,
                          float* __restrict__ hout)
{
    __shared__ float wsum[4], wsq[4];
    int row = blockIdx.x;
    int tid = threadIdx.x;
    const float4 v = *(const float4*)(x + (size_t)row * EMB + tid * 4);

    float s  = v.x + v.y + v.z + v.w;
    float sq = v.x * v.x + v.y * v.y + v.z * v.z + v.w * v.w;
    #pragma unroll
    for (int off = 16; off > 0; off >>= 1) {
        s  += __shfl_xor_sync(0xffffffffu, s,  off);
        sq += __shfl_xor_sync(0xffffffffu, sq, off);
    }
    int warp = tid >> 5;
    if ((tid & 31) == 0) { wsum[warp] = s; wsq[warp] = sq; }
    __syncthreads();
    float S  = wsum[0] + wsum[1] + wsum[2] + wsum[3];
    float SQ = wsq[0] + wsq[1] + wsq[2] + wsq[3];

    float mu  = S * (1.0f / EMB);
    float var = SQ * (1.0f / EMB) - mu * mu;
    float rinv = rsqrtf(var + 1e-5f);

    int c = tid * 4;
    float4 o;
    o.x = (v.x - mu) * rinv * gamma[c + 0] + beta[c + 0];
    o.y = (v.y - mu) * rinv * gamma[c + 1] + beta[c + 1];
    o.z = (v.z - mu) * rinv * gamma[c + 2] + beta[c + 2];
    o.w = (v.w - mu) * rinv * gamma[c + 3] + beta[c + 3];
    *(float4*)(hout + (size_t)row * EMB + c) = o;
}

// ---------------------------------------------------------------------------
// Transpose K per (b,h): (L rows x 64 d) slice of g_k -> g_kt[(b*8+h)][d][l]
// grid (L/32, HD/32, B*H), block (32,8)
// ---------------------------------------------------------------------------
__global__ void kt_transpose_kernel(const float* __restrict__ gk,
                                    float* __restrict__ gkt)
{
    __shared__ float t[32][33];
    int z  = blockIdx.z;           // bb*8 + hh
    int bb = z >> 3, hh = z & 7;
    int l0 = blockIdx.x * 32;
    int d0 = blockIdx.y * 32;
    int tx = threadIdx.x, ty = threadIdx.y;

    for (int r = ty; r < 32; r += 8)
        t[r][tx] = gk[((size_t)bb * Lq + l0 + r) * EMB + hh * HD + d0 + tx];
    __syncthreads();
    for (int r = ty; r < 32; r += 8)
        gkt[((size_t)z * HD + d0 + r) * Lq + l0 + tx] = t[tx][r];
}

// ---------------------------------------------------------------------------
// Transpose Er per head: (BS x HD) -> g_ert[h][d][p]
// grid (BS/32, HD/32, H), block (32,8)
// ---------------------------------------------------------------------------
__global__ void ert_transpose_kernel(const float* __restrict__ er,
                                     float* __restrict__ gert)
{
    __shared__ float t[32][33];
    int h  = blockIdx.z;
    int p0 = blockIdx.x * 32;
    int d0 = blockIdx.y * 32;
    int tx = threadIdx.x, ty = threadIdx.y;

    for (int r = ty; r < 32; r += 8)
        t[r][tx] = er[((size_t)h * BSz + p0 + r) * HD + d0 + tx];
    __syncthreads();
    for (int r = ty; r < 32; r += 8)
        gert[((size_t)h * HD + d0 + r) * BSz + p0 + tx] = t[tx][r];
}

// ---------------------------------------------------------------------------
// Generic SGEMM: C[M,N] = A[M,K] * B[K,N] + bias
// BM=BN=128, BK=8, 256 threads, 8x8 per thread.
// ---------------------------------------------------------------------------
__global__ void sgemm_kernel(int M, int N, int K,
                             const float* __restrict__ A, int lda,
                             const float* __restrict__ B, int ldb,
                             float* __restrict__ C, int ldc,
                             const float* __restrict__ bias)
{
    __shared__ float As[8][128];
    __shared__ float Bs[8][128];

    int bm = blockIdx.y, bn = blockIdx.x;
    int tid = threadIdx.x;
    int ty = tid >> 4, tx = tid & 15;

    const float* Ab = A + (size_t)bm * 128 * lda;
    const float* Bb = B + bn * 128;

    int arow = tid >> 1, acol = (tid & 1) * 4;
    int brow = tid >> 5, bcol = (tid & 31) * 4;

    float acc[8][8];
    #pragma unroll
    for (int i = 0; i < 8; i++)
        #pragma unroll
        for (int j = 0; j < 8; j++) acc[i][j] = 0.0f;

    for (int k0 = 0; k0 < K; k0 += 8) {
        float4 av = *(const float4*)(Ab + (size_t)arow * lda + k0 + acol);
        As[acol + 0][arow] = av.x;
        As[acol + 1][arow] = av.y;
        As[acol + 2][arow] = av.z;
        As[acol + 3][arow] = av.w;
        float4 bv = *(const float4*)(Bb + (size_t)(k0 + brow) * ldb + bcol);
        *(float4*)(&Bs[brow][bcol]) = bv;
        __syncthreads();

        #pragma unroll
        for (int k = 0; k < 8; k++) {
            float a[8], b[8];
            *(float4*)(a)     = *(const float4*)(&As[k][ty * 8]);
            *(float4*)(a + 4) = *(const float4*)(&As[k][ty * 8 + 4]);
            *(float4*)(b)     = *(const float4*)(&Bs[k][tx * 8]);
            *(float4*)(b + 4) = *(const float4*)(&Bs[k][tx * 8 + 4]);
            #pragma unroll
            for (int i = 0; i < 8; i++)
                #pragma unroll
                for (int j = 0; j < 8; j++)
                    acc[i][j] += a[i] * b[j];
        }
        __syncthreads();
    }

    #pragma unroll
    for (int i = 0; i < 8; i++) {
        int row = bm * 128 + ty * 8 + i;
        #pragma unroll
        for (int j = 0; j < 8; j += 4) {
            int col = bn * 128 + tx * 8 + j;
            float4 o;
            o.x = acc[i][j + 0] + (bias ? bias[col + 0] : 0.0f);
            o.y = acc[i][j + 1] + (bias ? bias[col + 1] : 0.0f);
            o.z = acc[i][j + 2] + (bias ? bias[col + 2] : 0.0f);
            o.w = acc[i][j + 3] + (bias ? bias[col + 3] : 0.0f);
            *(float4*)(C + (size_t)row * ldc + col) = o;
        }
    }
}

// ---------------------------------------------------------------------------
// Fused attention, register-blocked.
// Per (b,h), 32 query rows per block, 256 threads.
//   Pass A: E[r][p] = q[r].Er[p]  (regular GEMM, operands d-major) scattered
//           into sc at column (p + l) mod 1024.
//   Pass B: sc[r][j] = 0.125 * (q[r].k[j]) + sc[r][j]
//   Softmax rows of sc.
//   Pass C: out = P @ V, split-K across block halves.
// smem: sc[32][1036] | qt[64][36] | stage[8704]
// ---------------------------------------------------------------------------
#define SC_LD 1036
#define QT_LD 36
#define STAGE_FLOATS (2 * 64 * 68)
#define ATTN_SMEM_FLOATS (32 * SC_LD + 64 * QT_LD + STAGE_FLOATS)
#define ATTN_SMEM_BYTES  (ATTN_SMEM_FLOATS * 4)

__global__ __launch_bounds__(256, 1)
void attn_kernel(const float* __restrict__ gq,
                 const float* __restrict__ gkt,
                 const float* __restrict__ gv,
                 const float* __restrict__ gert,
                 float* __restrict__ gctx)
{
    extern __shared__ float sm[];
    float* sc  = sm;                               // [32][1036]
    float* qt  = sm + 32 * SC_LD;                  // [64][36] q transposed
    float* stg = sm + 32 * SC_LD + 64 * QT_LD;     // staging (Bs / V tiles / partial)

    int bh = blockIdx.y;
    int hh = bh & 7;
    int bb = bh >> 3;
    int l0 = blockIdx.x * 32;
    int tid = threadIdx.x;

    // ---- load q tile transposed: qt[d][r] ----
    {
        int r  = tid >> 3;
        int d4 = (tid & 7) * 8;
        const float* qp = gq + ((size_t)bb * Lq + l0 + r) * EMB + hh * HD;
        float4 v0 = *(const float4*)(qp + d4);
        float4 v1 = *(const float4*)(qp + d4 + 4);
        qt[(d4 + 0) * QT_LD + r] = v0.x;
        qt[(d4 + 1) * QT_LD + r] = v0.y;
        qt[(d4 + 2) * QT_LD + r] = v0.z;
        qt[(d4 + 3) * QT_LD + r] = v0.w;
        qt[(d4 + 4) * QT_LD + r] = v1.x;
        qt[(d4 + 5) * QT_LD + r] = v1.y;
        qt[(d4 + 6) * QT_LD + r] = v1.z;
        qt[(d4 + 7) * QT_LD + r] = v1.w;
    }

    int rg = tid >> 6;   // 4 row groups of 8 rows
    int cg = tid & 63;   // 64 col groups of 4 cols

    // ================= Pass A: QEr -> rotated scatter into sc =================
    const float* erh = gert + (size_t)hh * HD * BSz;  // [d][p]
    for (int pt = 0; pt < 4; pt++) {
        float acc[8][4];
        #pragma unroll
        for (int i = 0; i < 8; i++)
            #pragma unroll
            for (int c = 0; c < 4; c++) acc[i][c] = 0.0f;

        for (int dc = 0; dc < 8; dc++) {
            __syncthreads();
            // load Bs[8][256] from erT
            {
                const float* src = erh + (size_t)(dc * 8) * BSz + pt * 256;
                #pragma unroll
                for (int it = 0; it < 2; it++) {
                    int e = tid + it * 256;       // float4 index in [0,512)
                    int row  = e >> 6;
                    int col4 = (e & 63) * 4;
                    *(float4*)(stg + row * 256 + col4) =
                        *(const float4*)(src + (size_t)row * BSz + col4);
                }
            }
            __syncthreads();
            #pragma unroll
            for (int k = 0; k < 8; k++) {
                int d = dc * 8 + k;
                float a[8], b[4];
                *(float4*)(a)     = *(const float4*)(qt + d * QT_LD + rg * 8);
                *(float4*)(a + 4) = *(const float4*)(qt + d * QT_LD + rg * 8 + 4);
                *(float4*)(b)     = *(const float4*)(stg + k * 256 + cg * 4);
                #pragma unroll
                for (int i = 0; i < 8; i++)
                    #pragma unroll
                    for (int c = 0; c < 4; c++)
                        acc[i][c] += a[i] * b[c];
            }
        }
        // rotated scatter: col = (p + l) mod 1024
        #pragma unroll
        for (int i = 0; i < 8; i++) {
            int r = rg * 8 + i;
            int base = pt * 256 + cg * 4 + l0 + r;
            #pragma unroll
            for (int c = 0; c < 4; c++)
                sc[r * SC_LD + ((base + c) & (BSz - 1))] = acc[i][c];
        }
    }
    __syncthreads();

    // ================= Pass B: scores accumulate into sc =================
    const float* kth = gkt + (size_t)bh * HD * Lq;  // [d][j]
    for (int jt = 0; jt < 4; jt++) {
        float acc[8][4];
        #pragma unroll
        for (int i = 0; i < 8; i++)
            #pragma unroll
            for (int c = 0; c < 4; c++) acc[i][c] = 0.0f;

        for (int dc = 0; dc < 8; dc++) {
            __syncthreads();
            {
                const float* src = kth + (size_t)(dc * 8) * Lq + jt * 256;
                #pragma unroll
                for (int it = 0; it < 2; it++) {
                    int e = tid + it * 256;
                    int row  = e >> 6;
                    int col4 = (e & 63) * 4;
                    *(float4*)(stg + row * 256 + col4) =
                        *(const float4*)(src + (size_t)row * Lq + col4);
                }
            }
            __syncthreads();
            #pragma unroll
            for (int k = 0; k < 8; k++) {
                int d = dc * 8 + k;
                float a[8], b[4];
                *(float4*)(a)     = *(const float4*)(qt + d * QT_LD + rg * 8);
                *(float4*)(a + 4) = *(const float4*)(qt + d * QT_LD + rg * 8 + 4);
                *(float4*)(b)     = *(const float4*)(stg + k * 256 + cg * 4);
                #pragma unroll
                for (int i = 0; i < 8; i++)
                    #pragma unroll
                    for (int c = 0; c < 4; c++)
                        acc[i][c] += a[i] * b[c];
            }
        }
        #pragma unroll
        for (int i = 0; i < 8; i++) {
            int r = rg * 8 + i;
            float* p = sc + r * SC_LD + jt * 256 + cg * 4;
            #pragma unroll
            for (int c = 0; c < 4; c++)
                p[c] = fmaf(acc[i][c], 0.125f, p[c]);
        }
    }
    __syncthreads();

    // ================= Softmax over 1024 per row; 8 lanes per row =================
    {
        int warp = tid >> 5, lane = tid & 31;
        int row = warp * 4 + (lane >> 3);
        int sub = lane & 7;
        float* srow = sc + row * SC_LD;

        float m = -1e30f;
        for (int t = 0; t < 128; t++)
            m = fmaxf(m, srow[sub + t * 8]);
        #pragma unroll
        for (int off = 4; off > 0; off >>= 1)
            m = fmaxf(m, __shfl_xor_sync(0xffffffffu, m, off));

        float ssum = 0.0f;
        for (int t = 0; t < 128; t++) {
            float e = __expf(srow[sub + t * 8] - m);
            srow[sub + t * 8] = e;
            ssum += e;
        }
        #pragma unroll
        for (int off = 4; off > 0; off >>= 1)
            ssum += __shfl_xor_sync(0xffffffffu, ssum, off);

        float inv = 1.0f / ssum;
        for (int t = 0; t < 128; t++)
            srow[sub + t * 8] *= inv;
    }

    // ================= Pass C: out = P @ V, split-K across halves =================
    int half = tid >> 7;        // 0: keys 0..511, 1: keys 512..1023
    int ht   = tid & 127;
    int prg  = ht >> 4;         // 8 row groups of 4 rows
    int pdg  = ht & 15;         // 16 d groups of 4 d

    float oacc[4][4];
    #pragma unroll
    for (int i = 0; i < 4; i++)
        #pragma unroll
        for (int c = 0; c < 4; c++) oacc[i][c] = 0.0f;

    for (int t = 0; t < 8; t++) {
        __syncthreads();
        // stage two 64x64 V tiles: tile t (half 0) and tile 8+t (half 1)
        {
            #pragma unroll
            for (int it = 0; it < 8; it++) {
                int e = tid + it * 256;          // float4 idx in [0,2048)
                int s   = e >> 10;               // which tile
                int rem = e & 1023;
                int j   = rem >> 4;
                int d4  = (rem & 15) * 4;
                int keyTile = s * 8 + t;
                *(float4*)(stg + (s * 64 + j) * 68 + d4) =
                    *(const float4*)(gv + ((size_t)bb * Lq + keyTile * 64 + j) * EMB
                                     + hh * HD + d4);
            }
        }
        __syncthreads();

        const float* kvb = stg + half * 64 * 68;
        int jbase = (half * 8 + t) * 64;
        const float* scb = sc + jbase;
        #pragma unroll 2
        for (int jj = 0; jj < 64; jj++) {
            float b[4];
            *(float4*)(b) = *(const float4*)(kvb + jj * 68 + pdg * 4);
            float a0 = scb[(prg * 4 + 0) * SC_LD + jj];
            float a1 = scb[(prg * 4 + 1) * SC_LD + jj];
            float a2 = scb[(prg * 4 + 2) * SC_LD + jj];
            float a3 = scb[(prg * 4 + 3) * SC_LD + jj];
            #pragma unroll
            for (int c = 0; c < 4; c++) {
                oacc[0][c] += a0 * b[c];
                oacc[1][c] += a1 * b[c];
                oacc[2][c] += a2 * b[c];
                oacc[3][c] += a3 * b[c];
            }
        }
    }

    // reduce halves and store
    __syncthreads();
    float* part = stg;                           // [32][68]
    if (half == 1) {
        #pragma unroll
        for (int i = 0; i < 4; i++) {
            float4 o = make_float4(oacc[i][0], oacc[i][1], oacc[i][2], oacc[i][3]);
            *(float4*)(part + (prg * 4 + i) * 68 + pdg * 4) = o;
        }
    }
    __syncthreads();
    if (half == 0) {
        #pragma unroll
        for (int i = 0; i < 4; i++) {
            float4 p = *(const float4*)(part + (prg * 4 + i) * 68 + pdg * 4);
            float4 o = make_float4(oacc[i][0] + p.x, oacc[i][1] + p.y,
                                   oacc[i][2] + p.z, oacc[i][3] + p.w);
            *(float4*)(gctx + ((size_t)bb * Lq + l0 + prg * 4 + i) * EMB
                       + hh * HD + pdg * 4) = o;
        }
    }
}

// ---------------------------------------------------------------------------
extern "C" void kernel_launch(void* const* d_in, const int* in_sizes, int n_in,
                              void* d_out, int out_size)
{
    const float* x    = (const float*)d_in[0];
    const float* ln_g = (const float*)d_in[1];
    const float* ln_b = (const float*)d_in[2];
    const float* Wq   = (const float*)d_in[3];
    const float* bq   = (const float*)d_in[4];
    const float* Wk   = (const float*)d_in[5];
    const float* bk   = (const float*)d_in[6];
    const float* Wv   = (const float*)d_in[7];
    const float* bv   = (const float*)d_in[8];
    const float* Wo   = (const float*)d_in[9];
    const float* bo   = (const float*)d_in[10];
    const float* Er   = (const float*)d_in[11];
    float* out = (float*)d_out;

    float* scr = nullptr;
    cudaGetSymbolAddress((void**)&scr, g_scratch);
    float* g_h   = scr + OFF_H;
    float* g_q   = scr + OFF_Q;
    float* g_k   = scr + OFF_K;
    float* g_v   = scr + OFF_V;
    float* g_ctx = scr + OFF_CTX;
    float* g_kt  = scr + OFF_KT;
    float* g_ert = scr + OFF_ERT;

    // 1. LayerNorm
    ln_kernel<<<ROWS, 128>>>(x, ln_g, ln_b, g_h);

    // 2. QKV projections
    dim3 gProj(EMB / 128, ROWS / 128);  // (4, 64)
    sgemm_kernel<<<gProj, 256>>>(ROWS, EMB, EMB, g_h, EMB, Wq, EMB, g_q, EMB, bq);
    sgemm_kernel<<<gProj, 256>>>(ROWS, EMB, EMB, g_h, EMB, Wk, EMB, g_k, EMB, bk);
    sgemm_kernel<<<gProj, 256>>>(ROWS, EMB, EMB, g_h, EMB, Wv, EMB, g_v, EMB, bv);

    // 3. Transposes for d-major GEMM operands
    ert_transpose_kernel<<<dim3(BSz / 32, HD / 32, Hh), dim3(32, 8)>>>(Er, g_ert);
    kt_transpose_kernel<<<dim3(Lq / 32, HD / 32, Bq * Hh), dim3(32, 8)>>>(g_k, g_kt);

    // 4. Fused attention
    static bool attn_attr_set = false;
    if (!attn_attr_set) {
        cudaFuncSetAttribute(attn_kernel, cudaFuncAttributeMaxDynamicSharedMemorySize,
                             ATTN_SMEM_BYTES);
        attn_attr_set = true;
    }
    attn_kernel<<<dim3(Lq / 32, Bq * Hh), 256, ATTN_SMEM_BYTES>>>(g_q, g_kt, g_v, g_ert, g_ctx);

    // 5. Output projection
    sgemm_kernel<<<gProj, 256>>>(ROWS, EMB, EMB, g_ctx, EMB, Wo, EMB, out, EMB, bo);
}

// round 7
// speedup vs baseline: 2.2035x; 1.8745x over previous
#include <cuda_runtime.h>
#include <cstddef>

// ---------------------------------------------------------------------------
// RelAttnBlock: LN -> QKV proj -> rel-pos attention (QEr fused) -> O proj
// B=8, L=1024, EMB=512, H=8, HD=64, BS=1024
// ---------------------------------------------------------------------------

#define Bq 8
#define Lq 1024
#define EMB 512
#define Hh 8
#define HD 64
#define BSz 1024
#define ROWS (Bq * Lq)          // 8192

#define OFF_H    ((size_t)0)
#define OFF_Q    (OFF_H   + (size_t)ROWS * EMB)
#define OFF_K    (OFF_Q   + (size_t)ROWS * EMB)
#define OFF_V    (OFF_K   + (size_t)ROWS * EMB)
#define OFF_CTX  (OFF_V   + (size_t)ROWS * EMB)
#define OFF_KT   (OFF_CTX + (size_t)ROWS * EMB)              // (B*H, HD, L)
#define OFF_ERT  (OFF_KT  + (size_t)Bq * Hh * HD * Lq)       // (H, HD, BS)
#define SCRATCH_FLOATS (OFF_ERT + (size_t)Hh * HD * BSz)

__device__ float g_scratch[SCRATCH_FLOATS];

// ---------------------------------------------------------------------------
// LayerNorm
// ---------------------------------------------------------------------------
__global__ void ln_kernel(const float* __restrict__ x,
                          const float* __restrict__ gamma,
                          const float* __restrict__ beta,
                          float* __restrict__ hout)
{
    __shared__ float wsum[4], wsq[4];
    int row = blockIdx.x;
    int tid = threadIdx.x;
    const float4 v = *(const float4*)(x + (size_t)row * EMB + tid * 4);

    float s  = v.x + v.y + v.z + v.w;
    float sq = v.x * v.x + v.y * v.y + v.z * v.z + v.w * v.w;
    #pragma unroll
    for (int off = 16; off > 0; off >>= 1) {
        s  += __shfl_xor_sync(0xffffffffu, s,  off);
        sq += __shfl_xor_sync(0xffffffffu, sq, off);
    }
    int warp = tid >> 5;
    if ((tid & 31) == 0) { wsum[warp] = s; wsq[warp] = sq; }
    __syncthreads();
    float S  = wsum[0] + wsum[1] + wsum[2] + wsum[3];
    float SQ = wsq[0] + wsq[1] + wsq[2] + wsq[3];

    float mu  = S * (1.0f / EMB);
    float var = SQ * (1.0f / EMB) - mu * mu;
    float rinv = rsqrtf(var + 1e-5f);

    int c = tid * 4;
    float4 o;
    o.x = (v.x - mu) * rinv * gamma[c + 0] + beta[c + 0];
    o.y = (v.y - mu) * rinv * gamma[c + 1] + beta[c + 1];
    o.z = (v.z - mu) * rinv * gamma[c + 2] + beta[c + 2];
    o.w = (v.w - mu) * rinv * gamma[c + 3] + beta[c + 3];
    *(float4*)(hout + (size_t)row * EMB + c) = o;
}

// ---------------------------------------------------------------------------
// Transposes
// ---------------------------------------------------------------------------
__global__ void kt_transpose_kernel(const float* __restrict__ gk,
                                    float* __restrict__ gkt)
{
    __shared__ float t[32][33];
    int z  = blockIdx.z;
    int bb = z >> 3, hh = z & 7;
    int l0 = blockIdx.x * 32;
    int d0 = blockIdx.y * 32;
    int tx = threadIdx.x, ty = threadIdx.y;

    for (int r = ty; r < 32; r += 8)
        t[r][tx] = gk[((size_t)bb * Lq + l0 + r) * EMB + hh * HD + d0 + tx];
    __syncthreads();
    for (int r = ty; r < 32; r += 8)
        gkt[((size_t)z * HD + d0 + r) * Lq + l0 + tx] = t[tx][r];
}

__global__ void ert_transpose_kernel(const float* __restrict__ er,
                                     float* __restrict__ gert)
{
    __shared__ float t[32][33];
    int h  = blockIdx.z;
    int p0 = blockIdx.x * 32;
    int d0 = blockIdx.y * 32;
    int tx = threadIdx.x, ty = threadIdx.y;

    for (int r = ty; r < 32; r += 8)
        t[r][tx] = er[((size_t)h * BSz + p0 + r) * HD + d0 + tx];
    __syncthreads();
    for (int r = ty; r < 32; r += 8)
        gert[((size_t)h * HD + d0 + r) * BSz + p0 + tx] = t[tx][r];
}

// ---------------------------------------------------------------------------
// SGEMM, software-pipelined: double-buffered smem, register prefetch,
// ONE __syncthreads per K-chunk. BM=BN=128, BK=8, 256 threads, 8x8/thread.
// ---------------------------------------------------------------------------
__global__ __launch_bounds__(256, 2)
void sgemm_kernel(int M, int N, int K,
                  const float* __restrict__ A, int lda,
                  const float* __restrict__ B, int ldb,
                  float* __restrict__ C, int ldc,
                  const float* __restrict__ bias)
{
    __shared__ float As[2][8][128];
    __shared__ float Bs[2][8][128];

    int bm = blockIdx.y, bn = blockIdx.x;
    int tid = threadIdx.x;
    int ty = tid >> 4, tx = tid & 15;

    const float* Ab = A + (size_t)bm * 128 * lda;
    const float* Bb = B + bn * 128;

    int arow = tid >> 1, acol = (tid & 1) * 4;
    int brow = tid >> 5, bcol = (tid & 31) * 4;

    float acc[8][8];
    #pragma unroll
    for (int i = 0; i < 8; i++)
        #pragma unroll
        for (int j = 0; j < 8; j++) acc[i][j] = 0.0f;

    // prologue: tile 0 in registers
    float4 av = *(const float4*)(Ab + (size_t)arow * lda + acol);
    float4 bv = *(const float4*)(Bb + (size_t)brow * ldb + bcol);

    int nIter = K / 8;
    for (int it = 0; it < nIter; it++) {
        int buf = it & 1;
        As[buf][acol + 0][arow] = av.x;
        As[buf][acol + 1][arow] = av.y;
        As[buf][acol + 2][arow] = av.z;
        As[buf][acol + 3][arow] = av.w;
        *(float4*)(&Bs[buf][brow][bcol]) = bv;

        if (it + 1 < nIter) {
            int k0 = (it + 1) * 8;
            av = *(const float4*)(Ab + (size_t)arow * lda + k0 + acol);
            bv = *(const float4*)(Bb + (size_t)(k0 + brow) * ldb + bcol);
        }
        __syncthreads();

        #pragma unroll
        for (int k = 0; k < 8; k++) {
            float a[8], b[8];
            *(float4*)(a)     = *(const float4*)(&As[buf][k][ty * 8]);
            *(float4*)(a + 4) = *(const float4*)(&As[buf][k][ty * 8 + 4]);
            *(float4*)(b)     = *(const float4*)(&Bs[buf][k][tx * 8]);
            *(float4*)(b + 4) = *(const float4*)(&Bs[buf][k][tx * 8 + 4]);
            #pragma unroll
            for (int i = 0; i < 8; i++)
                #pragma unroll
                for (int j = 0; j < 8; j++)
                    acc[i][j] += a[i] * b[j];
        }
    }

    #pragma unroll
    for (int i = 0; i < 8; i++) {
        int row = bm * 128 + ty * 8 + i;
        #pragma unroll
        for (int j = 0; j < 8; j += 4) {
            int col = bn * 128 + tx * 8 + j;
            float4 o;
            o.x = acc[i][j + 0] + (bias ? bias[col + 0] : 0.0f);
            o.y = acc[i][j + 1] + (bias ? bias[col + 1] : 0.0f);
            o.z = acc[i][j + 2] + (bias ? bias[col + 2] : 0.0f);
            o.w = acc[i][j + 3] + (bias ? bias[col + 3] : 0.0f);
            *(float4*)(C + (size_t)row * ldc + col) = o;
        }
    }
}

// ---------------------------------------------------------------------------
// Fused attention, register-blocked + software-pipelined staging.
//   Pass A: E[r][p] = q[r].Er[p] scattered into sc at col (p+l) mod 1024
//   Pass B: sc[r][j] += 0.125 * q[r].k[j]
//   Softmax rows. Pass C: out = P @ V (split-K halves, 32-row V tiles).
// smem: sc[32][1036] | qt[64][36] | stg[8704] (double buffers)
// ---------------------------------------------------------------------------
#define SC_LD 1036
#define QT_LD 36
#define STG_FLOATS 8704
#define ATTN_SMEM_FLOATS (32 * SC_LD + 64 * QT_LD + STG_FLOATS)
#define ATTN_SMEM_BYTES  (ATTN_SMEM_FLOATS * 4)

__global__ __launch_bounds__(256, 1)
void attn_kernel(const float* __restrict__ gq,
                 const float* __restrict__ gkt,
                 const float* __restrict__ gv,
                 const float* __restrict__ gert,
                 float* __restrict__ gctx)
{
    extern __shared__ float sm[];
    float* sc  = sm;                               // [32][1036]
    float* qt  = sm + 32 * SC_LD;                  // [64][36]
    float* stg = sm + 32 * SC_LD + 64 * QT_LD;     // staging, double buffers

    int bh = blockIdx.y;
    int hh = bh & 7;
    int bb = bh >> 3;
    int l0 = blockIdx.x * 32;
    int tid = threadIdx.x;

    // ---- q tile transposed: qt[d][r] ----
    {
        int r  = tid >> 3;
        int d4 = (tid & 7) * 8;
        const float* qp = gq + ((size_t)bb * Lq + l0 + r) * EMB + hh * HD;
        float4 v0 = *(const float4*)(qp + d4);
        float4 v1 = *(const float4*)(qp + d4 + 4);
        qt[(d4 + 0) * QT_LD + r] = v0.x;
        qt[(d4 + 1) * QT_LD + r] = v0.y;
        qt[(d4 + 2) * QT_LD + r] = v0.z;
        qt[(d4 + 3) * QT_LD + r] = v0.w;
        qt[(d4 + 4) * QT_LD + r] = v1.x;
        qt[(d4 + 5) * QT_LD + r] = v1.y;
        qt[(d4 + 6) * QT_LD + r] = v1.z;
        qt[(d4 + 7) * QT_LD + r] = v1.w;
    }
    __syncthreads();

    int rg = tid >> 6;   // 4 row groups of 8 rows
    int cg = tid & 63;   // 64 col groups of 4 cols
    int stg_row  = tid >> 6;          // staging: rows 0..3 (+4 via it)
    int stg_col4 = (tid & 63) * 4;

    const float* erh = gert + (size_t)hh * HD * BSz;  // [d][p]
    const float* kth = gkt + (size_t)bh * HD * Lq;    // [d][j]

    // ================= Pass A: QEr -> rotated scatter =================
    for (int pt = 0; pt < 4; pt++) {
        float acc[8][4];
        #pragma unroll
        for (int i = 0; i < 8; i++)
            #pragma unroll
            for (int c = 0; c < 4; c++) acc[i][c] = 0.0f;

        float4 rv[2];
        {
            const float* src = erh + pt * 256;
            #pragma unroll
            for (int it = 0; it < 2; it++)
                rv[it] = *(const float4*)(src + (size_t)(stg_row + it * 4) * BSz + stg_col4);
        }
        for (int dc = 0; dc < 8; dc++) {
            float* sE = stg + (dc & 1) * 2048;
            #pragma unroll
            for (int it = 0; it < 2; it++)
                *(float4*)(sE + (stg_row + it * 4) * 256 + stg_col4) = rv[it];
            if (dc < 7) {
                const float* src = erh + (size_t)((dc + 1) * 8) * BSz + pt * 256;
                #pragma unroll
                for (int it = 0; it < 2; it++)
                    rv[it] = *(const float4*)(src + (size_t)(stg_row + it * 4) * BSz + stg_col4);
            }
            __syncthreads();
            #pragma unroll
            for (int k = 0; k < 8; k++) {
                int d = dc * 8 + k;
                float a[8], b[4];
                *(float4*)(a)     = *(const float4*)(qt + d * QT_LD + rg * 8);
                *(float4*)(a + 4) = *(const float4*)(qt + d * QT_LD + rg * 8 + 4);
                *(float4*)(b)     = *(const float4*)(sE + k * 256 + cg * 4);
                #pragma unroll
                for (int i = 0; i < 8; i++)
                    #pragma unroll
                    for (int c = 0; c < 4; c++)
                        acc[i][c] += a[i] * b[c];
            }
        }
        #pragma unroll
        for (int i = 0; i < 8; i++) {
            int r = rg * 8 + i;
            int base = pt * 256 + cg * 4 + l0 + r;
            #pragma unroll
            for (int c = 0; c < 4; c++)
                sc[r * SC_LD + ((base + c) & (BSz - 1))] = acc[i][c];
        }
    }

    // ================= Pass B: scores accumulate =================
    for (int jt = 0; jt < 4; jt++) {
        float acc[8][4];
        #pragma unroll
        for (int i = 0; i < 8; i++)
            #pragma unroll
            for (int c = 0; c < 4; c++) acc[i][c] = 0.0f;

        float4 rv[2];
        {
            const float* src = kth + jt * 256;
            #pragma unroll
            for (int it = 0; it < 2; it++)
                rv[it] = *(const float4*)(src + (size_t)(stg_row + it * 4) * Lq + stg_col4);
        }
        for (int dc = 0; dc < 8; dc++) {
            float* sK = stg + 4096 + (dc & 1) * 2048;
            #pragma unroll
            for (int it = 0; it < 2; it++)
                *(float4*)(sK + (stg_row + it * 4) * 256 + stg_col4) = rv[it];
            if (dc < 7) {
                const float* src = kth + (size_t)((dc + 1) * 8) * Lq + jt * 256;
                #pragma unroll
                for (int it = 0; it < 2; it++)
                    rv[it] = *(const float4*)(src + (size_t)(stg_row + it * 4) * Lq + stg_col4);
            }
            __syncthreads();
            #pragma unroll
            for (int k = 0; k < 8; k++) {
                int d = dc * 8 + k;
                float a[8], b[4];
                *(float4*)(a)     = *(const float4*)(qt + d * QT_LD + rg * 8);
                *(float4*)(a + 4) = *(const float4*)(qt + d * QT_LD + rg * 8 + 4);
                *(float4*)(b)     = *(const float4*)(sK + k * 256 + cg * 4);
                #pragma unroll
                for (int i = 0; i < 8; i++)
                    #pragma unroll
                    for (int c = 0; c < 4; c++)
                        acc[i][c] += a[i] * b[c];
            }
        }
        // sync so every thread's pass-A scatter is complete before we add into
        // those cells (covered by the dc-loop syncs of this jt iteration).
        #pragma unroll
        for (int i = 0; i < 8; i++) {
            int r = rg * 8 + i;
            float* p = sc + r * SC_LD + jt * 256 + cg * 4;
            #pragma unroll
            for (int c = 0; c < 4; c++)
                p[c] = fmaf(acc[i][c], 0.125f, p[c]);
        }
    }
    __syncthreads();

    // ---- Pass C prologue: issue first V-tile loads BEFORE softmax ----
    int half = tid >> 7;        // 0: keys 0..511, 1: keys 512..1023
    int ht   = tid & 127;
    int prg  = ht >> 4;         // 8 row groups of 4 rows
    int pdg  = ht & 15;         // 16 d groups of 4 d

    float4 cv[4];
    {
        #pragma unroll
        for (int it = 0; it < 4; it++) {
            int e   = tid + it * 256;        // [0,1024) float4
            int s   = e >> 9;                // half
            int rem = e & 511;
            int j   = rem >> 4;              // 0..31
            int d4  = (rem & 15) * 4;
            cv[it] = *(const float4*)(gv + ((size_t)bb * Lq + s * 512 + j) * EMB
                                      + hh * HD + d4);
        }
    }

    // ================= Softmax (hides pass-C prologue LDG) =================
    {
        int warp = tid >> 5, lane = tid & 31;
        int row = warp * 4 + (lane >> 3);
        int sub = lane & 7;
        float* srow = sc + row * SC_LD;

        float m = -1e30f;
        for (int t = 0; t < 128; t++)
            m = fmaxf(m, srow[sub + t * 8]);
        #pragma unroll
        for (int off = 4; off > 0; off >>= 1)
            m = fmaxf(m, __shfl_xor_sync(0xffffffffu, m, off));

        float ssum = 0.0f;
        for (int t = 0; t < 128; t++) {
            float e = __expf(srow[sub + t * 8] - m);
            srow[sub + t * 8] = e;
            ssum += e;
        }
        #pragma unroll
        for (int off = 4; off > 0; off >>= 1)
            ssum += __shfl_xor_sync(0xffffffffu, ssum, off);

        float inv = 1.0f / ssum;
        for (int t = 0; t < 128; t++)
            srow[sub + t * 8] *= inv;
    }
    __syncthreads();

    // ================= Pass C: out = P @ V, pipelined 32-row tiles =================
    float oacc[4][4];
    #pragma unroll
    for (int i = 0; i < 4; i++)
        #pragma unroll
        for (int c = 0; c < 4; c++) oacc[i][c] = 0.0f;

    for (int t = 0; t < 16; t++) {
        float* sV = stg + (t & 1) * 4352;     // [2][32][68]
        {
            #pragma unroll
            for (int it = 0; it < 4; it++) {
                int e   = tid + it * 256;
                int s   = e >> 9;
                int rem = e & 511;
                int j   = rem >> 4;
                int d4  = (rem & 15) * 4;
                *(float4*)(sV + s * 32 * 68 + j * 68 + d4) = cv[it];
            }
        }
        if (t < 15) {
            #pragma unroll
            for (int it = 0; it < 4; it++) {
                int e   = tid + it * 256;
                int s   = e >> 9;
                int rem = e & 511;
                int j   = rem >> 4;
                int d4  = (rem & 15) * 4;
                cv[it] = *(const float4*)(gv + ((size_t)bb * Lq + s * 512 + (t + 1) * 32 + j) * EMB
                                          + hh * HD + d4);
            }
        }
        __syncthreads();

        const float* kvb = stg + (t & 1) * 4352 + half * 32 * 68;
        const float* scb = sc + half * 512 + t * 32;
        #pragma unroll 2
        for (int jj = 0; jj < 32; jj++) {
            float b[4];
            *(float4*)(b) = *(const float4*)(kvb + jj * 68 + pdg * 4);
            float a0 = scb[(prg * 4 + 0) * SC_LD + jj];
            float a1 = scb[(prg * 4 + 1) * SC_LD + jj];
            float a2 = scb[(prg * 4 + 2) * SC_LD + jj];
            float a3 = scb[(prg * 4 + 3) * SC_LD + jj];
            #pragma unroll
            for (int c = 0; c < 4; c++) {
                oacc[0][c] += a0 * b[c];
                oacc[1][c] += a1 * b[c];
                oacc[2][c] += a2 * b[c];
                oacc[3][c] += a3 * b[c];
            }
        }
    }

    // reduce halves and store
    __syncthreads();
    float* part = stg;                           // [32][68]
    if (half == 1) {
        #pragma unroll
        for (int i = 0; i < 4; i++) {
            float4 o = make_float4(oacc[i][0], oacc[i][1], oacc[i][2], oacc[i][3]);
            *(float4*)(part + (prg * 4 + i) * 68 + pdg * 4) = o;
        }
    }
    __syncthreads();
    if (half == 0) {
        #pragma unroll
        for (int i = 0; i < 4; i++) {
            float4 p = *(const float4*)(part + (prg * 4 + i) * 68 + pdg * 4);
            float4 o = make_float4(oacc[i][0] + p.x, oacc[i][1] + p.y,
                                   oacc[i][2] + p.z, oacc[i][3] + p.w);
            *(float4*)(gctx + ((size_t)bb * Lq + l0 + prg * 4 + i) * EMB
                       + hh * HD + pdg * 4) = o;
        }
    }
}

// ---------------------------------------------------------------------------
extern "C" void kernel_launch(void* const* d_in, const int* in_sizes, int n_in,
                              void* d_out, int out_size)
{
    const float* x    = (const float*)d_in[0];
    const float* ln_g = (const float*)d_in[1];
    const float* ln_b = (const float*)d_in[2];
    const float* Wq   = (const float*)d_in[3];
    const float* bq   = (const float*)d_in[4];
    const float* Wk   = (const float*)d_in[5];
    const float* bk   = (const float*)d_in[6];
    const float* Wv   = (const float*)d_in[7];
    const float* bv   = (const float*)d_in[8];
    const float* Wo   = (const float*)d_in[9];
    const float* bo   = (const float*)d_in[10];
    const float* Er   = (const float*)d_in[11];
    float* out = (float*)d_out;

    float* scr = nullptr;
    cudaGetSymbolAddress((void**)&scr, g_scratch);
    float* g_h   = scr + OFF_H;
    float* g_q   = scr + OFF_Q;
    float* g_k   = scr + OFF_K;
    float* g_v   = scr + OFF_V;
    float* g_ctx = scr + OFF_CTX;
    float* g_kt  = scr + OFF_KT;
    float* g_ert = scr + OFF_ERT;

    // 1. LayerNorm
    ln_kernel<<<ROWS, 128>>>(x, ln_g, ln_b, g_h);

    // 2. QKV projections
    dim3 gProj(EMB / 128, ROWS / 128);  // (4, 64)
    sgemm_kernel<<<gProj, 256>>>(ROWS, EMB, EMB, g_h, EMB, Wq, EMB, g_q, EMB, bq);
    sgemm_kernel<<<gProj, 256>>>(ROWS, EMB, EMB, g_h, EMB, Wk, EMB, g_k, EMB, bk);
    sgemm_kernel<<<gProj, 256>>>(ROWS, EMB, EMB, g_h, EMB, Wv, EMB, g_v, EMB, bv);

    // 3. Transposes for d-major GEMM operands
    ert_transpose_kernel<<<dim3(BSz / 32, HD / 32, Hh), dim3(32, 8)>>>(Er, g_ert);
    kt_transpose_kernel<<<dim3(Lq / 32, HD / 32, Bq * Hh), dim3(32, 8)>>>(g_k, g_kt);

    // 4. Fused attention
    static bool attn_attr_set = false;
    if (!attn_attr_set) {
        cudaFuncSetAttribute(attn_kernel, cudaFuncAttributeMaxDynamicSharedMemorySize,
                             ATTN_SMEM_BYTES);
        attn_attr_set = true;
    }
    attn_kernel<<<dim3(Lq / 32, Bq * Hh), 256, ATTN_SMEM_BYTES>>>(g_q, g_kt, g_v, g_ert, g_ctx);

    // 5. Output projection
    sgemm_kernel<<<gProj, 256>>>(ROWS, EMB, EMB, g_ctx, EMB, Wo, EMB, out, EMB, bo);
}

// round 11
// speedup vs baseline: 2.6913x; 1.2214x over previous
#include <cuda_runtime.h>
#include <cuda_bf16.h>
#include <cstdint>
#include <cstddef>

// ---------------------------------------------------------------------------
// RelAttnBlock: LN -> QKV proj (HMMA bf16-split) -> rel-pos attention
//               -> O proj (HMMA). B=8, L=1024, EMB=512, H=8, HD=64, BS=1024
// tcgen05 rejected by this build's compute_103 PTX stage -> use mma.sync HMMA.
// ---------------------------------------------------------------------------

#define Bq 8
#define Lq 1024
#define EMB 512
#define Hh 8
#define HD 64
#define BSz 1024
#define ROWS (Bq * Lq)          // 8192

typedef __nv_bfloat16 bf16;

// Scratch layout (floats)
#define OFF_Q     ((size_t)0)
#define OFF_K     (OFF_Q    + (size_t)ROWS * EMB)
#define OFF_V     (OFF_K    + (size_t)ROWS * EMB)
#define OFF_KT    (OFF_V    + (size_t)ROWS * EMB)            // (B*H, HD, L)
#define OFF_ERT   (OFF_KT   + (size_t)Bq * Hh * HD * Lq)     // (H, HD, BS)
#define OFF_HHI   (OFF_ERT  + (size_t)Hh * HD * BSz)         // bf16 [8192][512]
#define OFF_HLO   (OFF_HHI  + (size_t)ROWS * EMB / 2)
#define OFF_CHI   (OFF_HLO  + (size_t)ROWS * EMB / 2)
#define OFF_CLO   (OFF_CHI  + (size_t)ROWS * EMB / 2)
#define OFF_WTHI  (OFF_CLO  + (size_t)ROWS * EMB / 2)        // bf16 [2048][512]
#define OFF_WTLO  (OFF_WTHI + (size_t)2048 * 512 / 2)
#define OFF_BIAS  (OFF_WTLO + (size_t)2048 * 512 / 2)
#define SCRATCH_FLOATS (OFF_BIAS + 2048)

__device__ float g_scratch[SCRATCH_FLOATS];

// ---------------------------------------------------------------------------
// PTX helpers (baseline PTX only: sm_80-class, compiles at compute_103)
// ---------------------------------------------------------------------------
__device__ __forceinline__ uint32_t smem_u32(const void* p) {
    uint32_t a;
    asm("{ .reg .u64 t; cvta.to.shared.u64 t, %1; cvt.u32.u64 %0, t; }"
        : "=r"(a) : "l"(p));
    return a;
}

#define CP_ASYNC16(saddr, gptr) \
    asm volatile("cp.async.cg.shared.global [%0], [%1], 16;" \
                 :: "r"(saddr), "l"(gptr) : "memory")
#define CP_COMMIT() asm volatile("cp.async.commit_group;" ::: "memory")
#define CP_WAIT1()  asm volatile("cp.async.wait_group 1;" ::: "memory")
#define CP_WAIT0()  asm volatile("cp.async.wait_group 0;" ::: "memory")

#define LDSM4(r0, r1, r2, r3, addr) \
    asm volatile("ldmatrix.sync.aligned.m8n8.x4.shared.b16 {%0,%1,%2,%3}, [%4];" \
                 : "=r"(r0), "=r"(r1), "=r"(r2), "=r"(r3) : "r"(addr))

#define MMA16816(c, a0, a1, a2, a3, b0, b1) \
    asm volatile("mma.sync.aligned.m16n8k16.row.col.f32.bf16.bf16.f32 " \
                 "{%0,%1,%2,%3}, {%4,%5,%6,%7}, {%8,%9}, {%0,%1,%2,%3};" \
                 : "+f"((c)[0]), "+f"((c)[1]), "+f"((c)[2]), "+f"((c)[3]) \
                 : "r"(a0), "r"(a1), "r"(a2), "r"(a3), "r"(b0), "r"(b1))

// ---------------------------------------------------------------------------
// LayerNorm -> bf16 hi/lo split outputs
// ---------------------------------------------------------------------------
__global__ void ln_kernel(const float* __restrict__ x,
                          const float* __restrict__ gamma,
                          const float* __restrict__ beta,
                          bf16* __restrict__ hhi,
                          bf16* __restrict__ hlo)
{
    __shared__ float wsum[4], wsq[4];
    int row = blockIdx.x;
    int tid = threadIdx.x;
    const float4 v = *(const float4*)(x + (size_t)row * EMB + tid * 4);

    float s  = v.x + v.y + v.z + v.w;
    float sq = v.x * v.x + v.y * v.y + v.z * v.z + v.w * v.w;
    #pragma unroll
    for (int off = 16; off > 0; off >>= 1) {
        s  += __shfl_xor_sync(0xffffffffu, s,  off);
        sq += __shfl_xor_sync(0xffffffffu, sq, off);
    }
    int warp = tid >> 5;
    if ((tid & 31) == 0) { wsum[warp] = s; wsq[warp] = sq; }
    __syncthreads();
    float S  = wsum[0] + wsum[1] + wsum[2] + wsum[3];
    float SQ = wsq[0] + wsq[1] + wsq[2] + wsq[3];

    float mu  = S * (1.0f / EMB);
    float var = SQ * (1.0f / EMB) - mu * mu;
    float rinv = rsqrtf(var + 1e-5f);

    int c = tid * 4;
    float o[4];
    o[0] = (v.x - mu) * rinv * gamma[c + 0] + beta[c + 0];
    o[1] = (v.y - mu) * rinv * gamma[c + 1] + beta[c + 1];
    o[2] = (v.z - mu) * rinv * gamma[c + 2] + beta[c + 2];
    o[3] = (v.w - mu) * rinv * gamma[c + 3] + beta[c + 3];

    __nv_bfloat162 hp[2], lp[2];
    #pragma unroll
    for (int i = 0; i < 2; i++) {
        bf16 h0 = __float2bfloat16(o[2 * i]);
        bf16 h1 = __float2bfloat16(o[2 * i + 1]);
        bf16 l0 = __float2bfloat16(o[2 * i]     - __bfloat162float(h0));
        bf16 l1 = __float2bfloat16(o[2 * i + 1] - __bfloat162float(h1));
        hp[i].x = h0; hp[i].y = h1;
        lp[i].x = l0; lp[i].y = l1;
    }
    size_t base = (size_t)row * EMB + c;
    *(__nv_bfloat162*)(hhi + base)     = hp[0];
    *(__nv_bfloat162*)(hhi + base + 2) = hp[1];
    *(__nv_bfloat162*)(hlo + base)     = lp[0];
    *(__nv_bfloat162*)(hlo + base + 2) = lp[1];
}

// ---------------------------------------------------------------------------
// Weight transpose + bf16 split: Wt[z*512 + n][k] = W_z[k][n]
// ---------------------------------------------------------------------------
__global__ void wt_convert_kernel(const float* __restrict__ Wq,
                                  const float* __restrict__ Wk,
                                  const float* __restrict__ Wv,
                                  const float* __restrict__ Wo,
                                  bf16* __restrict__ wthi,
                                  bf16* __restrict__ wtlo)
{
    __shared__ float t[32][33];
    int z  = blockIdx.z;
    const float* W = (z == 0) ? Wq : (z == 1) ? Wk : (z == 2) ? Wv : Wo;
    int n0 = blockIdx.x * 32;
    int k0 = blockIdx.y * 32;
    int tx = threadIdx.x, ty = threadIdx.y;

    for (int r = ty; r < 32; r += 8)
        t[r][tx] = W[(size_t)(k0 + r) * EMB + n0 + tx];
    __syncthreads();
    for (int r = ty; r < 32; r += 8) {
        float val = t[tx][r];
        bf16 h = __float2bfloat16(val);
        bf16 l = __float2bfloat16(val - __bfloat162float(h));
        size_t idx = (size_t)(z * 512 + n0 + r) * EMB + k0 + tx;
        wthi[idx] = h;
        wtlo[idx] = l;
    }
}

__global__ void bias_gather_kernel(const float* __restrict__ bq,
                                   const float* __restrict__ bk,
                                   const float* __restrict__ bv,
                                   const float* __restrict__ bo,
                                   float* __restrict__ out)
{
    int i = blockIdx.x * 256 + threadIdx.x;
    if (i >= 2048) return;
    int sel = i >> 9;
    const float* b = (sel == 0) ? bq : (sel == 1) ? bk : (sel == 2) ? bv : bo;
    out[i] = b[i & 511];
}

// ---------------------------------------------------------------------------
// Transposes
// ---------------------------------------------------------------------------
__global__ void kt_transpose_kernel(const float* __restrict__ gk,
                                    float* __restrict__ gkt)
{
    __shared__ float t[32][33];
    int z  = blockIdx.z;
    int bb = z >> 3, hh = z & 7;
    int l0 = blockIdx.x * 32;
    int d0 = blockIdx.y * 32;
    int tx = threadIdx.x, ty = threadIdx.y;

    for (int r = ty; r < 32; r += 8)
        t[r][tx] = gk[((size_t)bb * Lq + l0 + r) * EMB + hh * HD + d0 + tx];
    __syncthreads();
    for (int r = ty; r < 32; r += 8)
        gkt[((size_t)z * HD + d0 + r) * Lq + l0 + tx] = t[tx][r];
}

__global__ void ert_transpose_kernel(const float* __restrict__ er,
                                     float* __restrict__ gert)
{
    __shared__ float t[32][33];
    int h  = blockIdx.z;
    int p0 = blockIdx.x * 32;
    int d0 = blockIdx.y * 32;
    int tx = threadIdx.x, ty = threadIdx.y;

    for (int r = ty; r < 32; r += 8)
        t[r][tx] = er[((size_t)h * BSz + p0 + r) * HD + d0 + tx];
    __syncthreads();
    for (int r = ty; r < 32; r += 8)
        gert[((size_t)h * HD + d0 + r) * BSz + p0 + tx] = t[tx][r];
}

// ---------------------------------------------------------------------------
// HMMA bf16 split GEMM: C[m][n] = sum_k A[m][k]*Wt[n][k] + bias[n]
//   acc = Ahi*Bhi + Alo*Bhi + Ahi*Blo, fp32 accum in registers.
// CTA tile 128x128; 8 warps (4m x 2n), warp tile 32m x 64n.
// K-chunk 32; cp.async 2-stage pipeline.
// smem per stage: 4 tiles [128 rows][80B] (rows padded 64B->80B: 5 granules,
// 5 coprime 8 => ldmatrix conflict-free). Stage = 40960B, total 81920B.
// ---------------------------------------------------------------------------
#define TILE_B   (128 * 80)       // bytes per operand tile
#define STG_B    (4 * TILE_B)     // 40960
#define GEMM_SMEM_BYTES (2 * STG_B)

__global__ __launch_bounds__(256)
void hmma_gemm_kernel(const bf16* __restrict__ Ahi, const bf16* __restrict__ Alo,
                      const bf16* __restrict__ Bhi, const bf16* __restrict__ Blo,
                      const float* __restrict__ bias, int n0,
                      float* __restrict__ o0, float* __restrict__ o1,
                      float* __restrict__ o2, float* __restrict__ o3)
{
    extern __shared__ char smem[];
    uint32_t sbase = smem_u32(smem);

    int tid  = threadIdx.x;
    int wid  = tid >> 5;
    int lane = tid & 31;

    int m0     = blockIdx.y * 128;
    int nglob0 = n0 + blockIdx.x * 128;

    int warp_m = wid & 3;   // 0..3 -> 32 rows each
    int warp_n = wid >> 2;  // 0..1 -> 64 cols each

    float acc[2][8][4];
    #pragma unroll
    for (int mf = 0; mf < 2; mf++)
        #pragma unroll
        for (int nf = 0; nf < 8; nf++)
            #pragma unroll
            for (int e = 0; e < 4; e++) acc[mf][nf][e] = 0.0f;

    // per-thread cp.async granule map: G = tid + i*256 -> row=G>>2, cg=G&3
    int cp_row0 = tid >> 2;          // G = tid
    int cp_cg0  = tid & 3;
    int cp_row1 = (tid + 256) >> 2;  // G = tid + 256
    int cp_cg1  = (tid + 256) & 3;

    // ldmatrix addresses (relative to tile base)
    int a_row = warp_m * 32 + (lane & 15);
    int a_kg  = lane >> 4;                           // 0..1
    int b_row = warp_n * 64 + (lane & 7) + ((lane >> 4) << 3);
    int b_kg  = (lane >> 3) & 1;

    #define ISSUE_CHUNK(c) do {                                               \
        uint32_t st_ = sbase + ((c) & 1) * STG_B;                             \
        const bf16* gA0 = Ahi + (size_t)(m0 + cp_row0) * EMB + (c) * 32 + cp_cg0 * 8; \
        const bf16* gA1 = Ahi + (size_t)(m0 + cp_row1) * EMB + (c) * 32 + cp_cg1 * 8; \
        CP_ASYNC16(st_ + 0 * TILE_B + cp_row0 * 80 + cp_cg0 * 16, gA0);       \
        CP_ASYNC16(st_ + 0 * TILE_B + cp_row1 * 80 + cp_cg1 * 16, gA1);       \
        const bf16* gL0 = Alo + (size_t)(m0 + cp_row0) * EMB + (c) * 32 + cp_cg0 * 8; \
        const bf16* gL1 = Alo + (size_t)(m0 + cp_row1) * EMB + (c) * 32 + cp_cg1 * 8; \
        CP_ASYNC16(st_ + 1 * TILE_B + cp_row0 * 80 + cp_cg0 * 16, gL0);       \
        CP_ASYNC16(st_ + 1 * TILE_B + cp_row1 * 80 + cp_cg1 * 16, gL1);       \
        const bf16* gB0 = Bhi + (size_t)(nglob0 + cp_row0) * EMB + (c) * 32 + cp_cg0 * 8; \
        const bf16* gB1 = Bhi + (size_t)(nglob0 + cp_row1) * EMB + (c) * 32 + cp_cg1 * 8; \
        CP_ASYNC16(st_ + 2 * TILE_B + cp_row0 * 80 + cp_cg0 * 16, gB0);       \
        CP_ASYNC16(st_ + 2 * TILE_B + cp_row1 * 80 + cp_cg1 * 16, gB1);       \
        const bf16* gC0 = Blo + (size_t)(nglob0 + cp_row0) * EMB + (c) * 32 + cp_cg0 * 8; \
        const bf16* gC1 = Blo + (size_t)(nglob0 + cp_row1) * EMB + (c) * 32 + cp_cg1 * 8; \
        CP_ASYNC16(st_ + 3 * TILE_B + cp_row0 * 80 + cp_cg0 * 16, gC0);       \
        CP_ASYNC16(st_ + 3 * TILE_B + cp_row1 * 80 + cp_cg1 * 16, gC1);       \
        CP_COMMIT();                                                          \
    } while (0)

    ISSUE_CHUNK(0);

    for (int c = 0; c < 16; c++) {
        if (c + 1 < 16) { ISSUE_CHUNK(c + 1); CP_WAIT1(); }
        else            { CP_WAIT0(); }
        __syncthreads();

        uint32_t st = sbase + (c & 1) * STG_B;
        #pragma unroll
        for (int s = 0; s < 2; s++) {
            uint32_t aoff = (uint32_t)(a_row * 80 + (s * 2 + a_kg) * 16);
            uint32_t boff = (uint32_t)(b_row * 80 + (s * 2 + b_kg) * 16);

            // A hi frags (2 mfrags)
            uint32_t ah[2][4];
            LDSM4(ah[0][0], ah[0][1], ah[0][2], ah[0][3], st + 0 * TILE_B + aoff);
            LDSM4(ah[1][0], ah[1][1], ah[1][2], ah[1][3], st + 0 * TILE_B + aoff + 16 * 80);

            // B hi frags (4 x4 -> 8 nfrags)
            uint32_t bh[4][4];
            #pragma unroll
            for (int p = 0; p < 4; p++)
                LDSM4(bh[p][0], bh[p][1], bh[p][2], bh[p][3],
                      st + 2 * TILE_B + boff + p * 16 * 80);

            // pass 1: Ahi x Bhi
            #pragma unroll
            for (int mf = 0; mf < 2; mf++)
                #pragma unroll
                for (int nf = 0; nf < 8; nf++) {
                    int p = nf >> 1, q = (nf & 1) * 2;
                    MMA16816(acc[mf][nf], ah[mf][0], ah[mf][1], ah[mf][2], ah[mf][3],
                             bh[p][q], bh[p][q + 1]);
                }

            // pass 2: Alo x Bhi
            uint32_t al[2][4];
            LDSM4(al[0][0], al[0][1], al[0][2], al[0][3], st + 1 * TILE_B + aoff);
            LDSM4(al[1][0], al[1][1], al[1][2], al[1][3], st + 1 * TILE_B + aoff + 16 * 80);
            #pragma unroll
            for (int mf = 0; mf < 2; mf++)
                #pragma unroll
                for (int nf = 0; nf < 8; nf++) {
                    int p = nf >> 1, q = (nf & 1) * 2;
                    MMA16816(acc[mf][nf], al[mf][0], al[mf][1], al[mf][2], al[mf][3],
                             bh[p][q], bh[p][q + 1]);
                }

            // pass 3: Ahi x Blo (reuse bh regs)
            #pragma unroll
            for (int p = 0; p < 4; p++)
                LDSM4(bh[p][0], bh[p][1], bh[p][2], bh[p][3],
                      st + 3 * TILE_B + boff + p * 16 * 80);
            #pragma unroll
            for (int mf = 0; mf < 2; mf++)
                #pragma unroll
                for (int nf = 0; nf < 8; nf++) {
                    int p = nf >> 1, q = (nf & 1) * 2;
                    MMA16816(acc[mf][nf], ah[mf][0], ah[mf][1], ah[mf][2], ah[mf][3],
                             bh[p][q], bh[p][q + 1]);
                }
        }
        __syncthreads();
    }

    // Epilogue: bias + store. sel constant per CTA (128 | 512).
    int sel = nglob0 >> 9;
    float* outp = (sel == 0) ? o0 : (sel == 1) ? o1 : (sel == 2) ? o2 : o3;
    int ncol0 = (nglob0 & 511) + warp_n * 64;
    int g  = lane >> 2;
    int tg = lane & 3;

    #pragma unroll
    for (int mf = 0; mf < 2; mf++) {
        int r0 = m0 + warp_m * 32 + mf * 16 + g;
        #pragma unroll
        for (int nf = 0; nf < 8; nf++) {
            int col = ncol0 + nf * 8 + 2 * tg;
            int bcol = nglob0 - (nglob0 & 511) + col;  // global bias index
            float b0 = bias[bcol], b1 = bias[bcol + 1];
            float2 v0 = make_float2(acc[mf][nf][0] + b0, acc[mf][nf][1] + b1);
            float2 v1 = make_float2(acc[mf][nf][2] + b0, acc[mf][nf][3] + b1);
            *(float2*)(outp + (size_t)r0 * EMB + col)       = v0;
            *(float2*)(outp + (size_t)(r0 + 8) * EMB + col) = v1;
        }
    }
}

// ---------------------------------------------------------------------------
// Fused attention (round-7 structure; epilogue emits ctx hi/lo bf16)
// ---------------------------------------------------------------------------
#define SC_LD 1036
#define QT_LD 36
#define STG_FLOATS 8704
#define ATTN_SMEM_FLOATS (32 * SC_LD + 64 * QT_LD + STG_FLOATS)
#define ATTN_SMEM_BYTES  (ATTN_SMEM_FLOATS * 4)

__global__ __launch_bounds__(256, 1)
void attn_kernel(const float* __restrict__ gq,
                 const float* __restrict__ gkt,
                 const float* __restrict__ gv,
                 const float* __restrict__ gert,
                 bf16* __restrict__ chi,
                 bf16* __restrict__ clo)
{
    extern __shared__ float smf[];
    float* sc  = smf;
    float* qt  = smf + 32 * SC_LD;
    float* stg = smf + 32 * SC_LD + 64 * QT_LD;

    int bh = blockIdx.y;
    int hh = bh & 7;
    int bb = bh >> 3;
    int l0 = blockIdx.x * 32;
    int tid = threadIdx.x;

    {
        int r  = tid >> 3;
        int d4 = (tid & 7) * 8;
        const float* qp = gq + ((size_t)bb * Lq + l0 + r) * EMB + hh * HD;
        float4 v0 = *(const float4*)(qp + d4);
        float4 v1 = *(const float4*)(qp + d4 + 4);
        qt[(d4 + 0) * QT_LD + r] = v0.x;
        qt[(d4 + 1) * QT_LD + r] = v0.y;
        qt[(d4 + 2) * QT_LD + r] = v0.z;
        qt[(d4 + 3) * QT_LD + r] = v0.w;
        qt[(d4 + 4) * QT_LD + r] = v1.x;
        qt[(d4 + 5) * QT_LD + r] = v1.y;
        qt[(d4 + 6) * QT_LD + r] = v1.z;
        qt[(d4 + 7) * QT_LD + r] = v1.w;
    }
    __syncthreads();

    int rg = tid >> 6;
    int cg = tid & 63;
    int stg_row  = tid >> 6;
    int stg_col4 = (tid & 63) * 4;

    const float* erh = gert + (size_t)hh * HD * BSz;
    const float* kth = gkt + (size_t)bh * HD * Lq;

    // Pass A: QEr -> rotated scatter
    for (int pt = 0; pt < 4; pt++) {
        float acc[8][4];
        #pragma unroll
        for (int i = 0; i < 8; i++)
            #pragma unroll
            for (int c = 0; c < 4; c++) acc[i][c] = 0.0f;

        float4 rv[2];
        {
            const float* src = erh + pt * 256;
            #pragma unroll
            for (int it = 0; it < 2; it++)
                rv[it] = *(const float4*)(src + (size_t)(stg_row + it * 4) * BSz + stg_col4);
        }
        for (int dc = 0; dc < 8; dc++) {
            float* sE = stg + (dc & 1) * 2048;
            #pragma unroll
            for (int it = 0; it < 2; it++)
                *(float4*)(sE + (stg_row + it * 4) * 256 + stg_col4) = rv[it];
            if (dc < 7) {
                const float* src = erh + (size_t)((dc + 1) * 8) * BSz + pt * 256;
                #pragma unroll
                for (int it = 0; it < 2; it++)
                    rv[it] = *(const float4*)(src + (size_t)(stg_row + it * 4) * BSz + stg_col4);
            }
            __syncthreads();
            #pragma unroll
            for (int k = 0; k < 8; k++) {
                int d = dc * 8 + k;
                float a[8], b[4];
                *(float4*)(a)     = *(const float4*)(qt + d * QT_LD + rg * 8);
                *(float4*)(a + 4) = *(const float4*)(qt + d * QT_LD + rg * 8 + 4);
                *(float4*)(b)     = *(const float4*)(sE + k * 256 + cg * 4);
                #pragma unroll
                for (int i = 0; i < 8; i++)
                    #pragma unroll
                    for (int c = 0; c < 4; c++)
                        acc[i][c] += a[i] * b[c];
            }
        }
        #pragma unroll
        for (int i = 0; i < 8; i++) {
            int r = rg * 8 + i;
            int base = pt * 256 + cg * 4 + l0 + r;
            #pragma unroll
            for (int c = 0; c < 4; c++)
                sc[r * SC_LD + ((base + c) & (BSz - 1))] = acc[i][c];
        }
    }

    // Pass B: scores accumulate
    for (int jt = 0; jt < 4; jt++) {
        float acc[8][4];
        #pragma unroll
        for (int i = 0; i < 8; i++)
            #pragma unroll
            for (int c = 0; c < 4; c++) acc[i][c] = 0.0f;

        float4 rv[2];
        {
            const float* src = kth + jt * 256;
            #pragma unroll
            for (int it = 0; it < 2; it++)
                rv[it] = *(const float4*)(src + (size_t)(stg_row + it * 4) * Lq + stg_col4);
        }
        for (int dc = 0; dc < 8; dc++) {
            float* sK = stg + 4096 + (dc & 1) * 2048;
            #pragma unroll
            for (int it = 0; it < 2; it++)
                *(float4*)(sK + (stg_row + it * 4) * 256 + stg_col4) = rv[it];
            if (dc < 7) {
                const float* src = kth + (size_t)((dc + 1) * 8) * Lq + jt * 256;
                #pragma unroll
                for (int it = 0; it < 2; it++)
                    rv[it] = *(const float4*)(src + (size_t)(stg_row + it * 4) * Lq + stg_col4);
            }
            __syncthreads();
            #pragma unroll
            for (int k = 0; k < 8; k++) {
                int d = dc * 8 + k;
                float a[8], b[4];
                *(float4*)(a)     = *(const float4*)(qt + d * QT_LD + rg * 8);
                *(float4*)(a + 4) = *(const float4*)(qt + d * QT_LD + rg * 8 + 4);
                *(float4*)(b)     = *(const float4*)(sK + k * 256 + cg * 4);
                #pragma unroll
                for (int i = 0; i < 8; i++)
                    #pragma unroll
                    for (int c = 0; c < 4; c++)
                        acc[i][c] += a[i] * b[c];
            }
        }
        #pragma unroll
        for (int i = 0; i < 8; i++) {
            int r = rg * 8 + i;
            float* p = sc + r * SC_LD + jt * 256 + cg * 4;
            #pragma unroll
            for (int c = 0; c < 4; c++)
                p[c] = fmaf(acc[i][c], 0.125f, p[c]);
        }
    }
    __syncthreads();

    // Pass C prologue loads (hidden under softmax)
    int half = tid >> 7;
    int ht   = tid & 127;
    int prg  = ht >> 4;
    int pdg  = ht & 15;

    float4 cv[4];
    {
        #pragma unroll
        for (int it = 0; it < 4; it++) {
            int e   = tid + it * 256;
            int s   = e >> 9;
            int rem = e & 511;
            int j   = rem >> 4;
            int d4  = (rem & 15) * 4;
            cv[it] = *(const float4*)(gv + ((size_t)bb * Lq + s * 512 + j) * EMB
                                      + hh * HD + d4);
        }
    }

    // Softmax
    {
        int warp = tid >> 5, lane = tid & 31;
        int row = warp * 4 + (lane >> 3);
        int sub = lane & 7;
        float* srow = sc + row * SC_LD;

        float m = -1e30f;
        for (int t = 0; t < 128; t++)
            m = fmaxf(m, srow[sub + t * 8]);
        #pragma unroll
        for (int off = 4; off > 0; off >>= 1)
            m = fmaxf(m, __shfl_xor_sync(0xffffffffu, m, off));

        float ssum = 0.0f;
        for (int t = 0; t < 128; t++) {
            float e = __expf(srow[sub + t * 8] - m);
            srow[sub + t * 8] = e;
            ssum += e;
        }
        #pragma unroll
        for (int off = 4; off > 0; off >>= 1)
            ssum += __shfl_xor_sync(0xffffffffu, ssum, off);

        float inv = 1.0f / ssum;
        for (int t = 0; t < 128; t++)
            srow[sub + t * 8] *= inv;
    }
    __syncthreads();

    // Pass C: out = P @ V
    float oacc[4][4];
    #pragma unroll
    for (int i = 0; i < 4; i++)
        #pragma unroll
        for (int c = 0; c < 4; c++) oacc[i][c] = 0.0f;

    for (int t = 0; t < 16; t++) {
        float* sV = stg + (t & 1) * 4352;
        {
            #pragma unroll
            for (int it = 0; it < 4; it++) {
                int e   = tid + it * 256;
                int s   = e >> 9;
                int rem = e & 511;
                int j   = rem >> 4;
                int d4  = (rem & 15) * 4;
                *(float4*)(sV + s * 32 * 68 + j * 68 + d4) = cv[it];
            }
        }
        if (t < 15) {
            #pragma unroll
            for (int it = 0; it < 4; it++) {
                int e   = tid + it * 256;
                int s   = e >> 9;
                int rem = e & 511;
                int j   = rem >> 4;
                int d4  = (rem & 15) * 4;
                cv[it] = *(const float4*)(gv + ((size_t)bb * Lq + s * 512 + (t + 1) * 32 + j) * EMB
                                          + hh * HD + d4);
            }
        }
        __syncthreads();

        const float* kvb = stg + (t & 1) * 4352 + half * 32 * 68;
        const float* scb = sc + half * 512 + t * 32;
        #pragma unroll 2
        for (int jj = 0; jj < 32; jj++) {
            float b[4];
            *(float4*)(b) = *(const float4*)(kvb + jj * 68 + pdg * 4);
            float a0 = scb[(prg * 4 + 0) * SC_LD + jj];
            float a1 = scb[(prg * 4 + 1) * SC_LD + jj];
            float a2 = scb[(prg * 4 + 2) * SC_LD + jj];
            float a3 = scb[(prg * 4 + 3) * SC_LD + jj];
            #pragma unroll
            for (int c = 0; c < 4; c++) {
                oacc[0][c] += a0 * b[c];
                oacc[1][c] += a1 * b[c];
                oacc[2][c] += a2 * b[c];
                oacc[3][c] += a3 * b[c];
            }
        }
    }

    // reduce halves; emit ctx hi/lo bf16
    __syncthreads();
    float* part = stg;
    if (half == 1) {
        #pragma unroll
        for (int i = 0; i < 4; i++) {
            float4 o = make_float4(oacc[i][0], oacc[i][1], oacc[i][2], oacc[i][3]);
            *(float4*)(part + (prg * 4 + i) * 68 + pdg * 4) = o;
        }
    }
    __syncthreads();
    if (half == 0) {
        #pragma unroll
        for (int i = 0; i < 4; i++) {
            float4 p = *(const float4*)(part + (prg * 4 + i) * 68 + pdg * 4);
            float vals[4] = {oacc[i][0] + p.x, oacc[i][1] + p.y,
                             oacc[i][2] + p.z, oacc[i][3] + p.w};
            size_t base = ((size_t)bb * Lq + l0 + prg * 4 + i) * EMB + hh * HD + pdg * 4;
            __nv_bfloat162 hp[2], lp[2];
            #pragma unroll
            for (int u = 0; u < 2; u++) {
                bf16 h0 = __float2bfloat16(vals[2 * u]);
                bf16 h1 = __float2bfloat16(vals[2 * u + 1]);
                bf16 l0 = __float2bfloat16(vals[2 * u]     - __bfloat162float(h0));
                bf16 l1 = __float2bfloat16(vals[2 * u + 1] - __bfloat162float(h1));
                hp[u].x = h0; hp[u].y = h1;
                lp[u].x = l0; lp[u].y = l1;
            }
            *(__nv_bfloat162*)(chi + base)     = hp[0];
            *(__nv_bfloat162*)(chi + base + 2) = hp[1];
            *(__nv_bfloat162*)(clo + base)     = lp[0];
            *(__nv_bfloat162*)(clo + base + 2) = lp[1];
        }
    }
}

// ---------------------------------------------------------------------------
extern "C" void kernel_launch(void* const* d_in, const int* in_sizes, int n_in,
                              void* d_out, int out_size)
{
    const float* x    = (const float*)d_in[0];
    const float* ln_g = (const float*)d_in[1];
    const float* ln_b = (const float*)d_in[2];
    const float* Wq   = (const float*)d_in[3];
    const float* bq   = (const float*)d_in[4];
    const float* Wk   = (const float*)d_in[5];
    const float* bk   = (const float*)d_in[6];
    const float* Wv   = (const float*)d_in[7];
    const float* bv   = (const float*)d_in[8];
    const float* Wo   = (const float*)d_in[9];
    const float* bo   = (const float*)d_in[10];
    const float* Er   = (const float*)d_in[11];
    float* out = (float*)d_out;

    float* scr = nullptr;
    cudaGetSymbolAddress((void**)&scr, g_scratch);
    float* g_q    = scr + OFF_Q;
    float* g_k    = scr + OFF_K;
    float* g_v    = scr + OFF_V;
    float* g_kt   = scr + OFF_KT;
    float* g_ert  = scr + OFF_ERT;
    bf16*  g_hhi  = (bf16*)(scr + OFF_HHI);
    bf16*  g_hlo  = (bf16*)(scr + OFF_HLO);
    bf16*  g_chi  = (bf16*)(scr + OFF_CHI);
    bf16*  g_clo  = (bf16*)(scr + OFF_CLO);
    bf16*  g_wthi = (bf16*)(scr + OFF_WTHI);
    bf16*  g_wtlo = (bf16*)(scr + OFF_WTLO);
    float* g_bias = scr + OFF_BIAS;

    static bool attr_set = false;
    if (!attr_set) {
        cudaFuncSetAttribute(attn_kernel, cudaFuncAttributeMaxDynamicSharedMemorySize,
                             ATTN_SMEM_BYTES);
        cudaFuncSetAttribute(hmma_gemm_kernel, cudaFuncAttributeMaxDynamicSharedMemorySize,
                             GEMM_SMEM_BYTES);
        attr_set = true;
    }

    // 1. LayerNorm -> h hi/lo (bf16)
    ln_kernel<<<ROWS, 128>>>(x, ln_g, ln_b, g_hhi, g_hlo);

    // 2. Weight transpose+split, bias gather, Er transpose
    wt_convert_kernel<<<dim3(16, 16, 4), dim3(32, 8)>>>(Wq, Wk, Wv, Wo, g_wthi, g_wtlo);
    bias_gather_kernel<<<8, 256>>>(bq, bk, bv, bo, g_bias);
    ert_transpose_kernel<<<dim3(BSz / 32, HD / 32, Hh), dim3(32, 8)>>>(Er, g_ert);

    // 3. QKV projection: HMMA GEMM, N = 1536
    hmma_gemm_kernel<<<dim3(12, 64), 256, GEMM_SMEM_BYTES>>>(
        g_hhi, g_hlo, g_wthi, g_wtlo, g_bias, 0, g_q, g_k, g_v, out);

    // 4. K transpose
    kt_transpose_kernel<<<dim3(Lq / 32, HD / 32, Bq * Hh), dim3(32, 8)>>>(g_k, g_kt);

    // 5. Fused attention -> ctx hi/lo (bf16)
    attn_kernel<<<dim3(Lq / 32, Bq * Hh), 256, ATTN_SMEM_BYTES>>>(
        g_q, g_kt, g_v, g_ert, g_chi, g_clo);

    // 6. O projection: HMMA GEMM, N in [1536, 2048) -> d_out
    hmma_gemm_kernel<<<dim3(4, 64), 256, GEMM_SMEM_BYTES>>>(
        g_chi, g_clo, g_wthi, g_wtlo, g_bias, 1536, g_q, g_k, g_v, out);
}

// round 15
// speedup vs baseline: 4.6964x; 1.7450x over previous
#include <cuda_runtime.h>
#include <cuda_bf16.h>
#include <cuda_fp16.h>
#include <cstdint>
#include <cstddef>

// ---------------------------------------------------------------------------
// RelAttnBlock: LN -> QKV proj (HMMA bf16-split) -> rel-pos attention (HMMA
// fp16 2-pass split) -> O proj (HMMA). B=8, L=1024, EMB=512, H=8, HD=64
// ---------------------------------------------------------------------------

#define Bq 8
#define Lq 1024
#define EMB 512
#define Hh 8
#define HD 64
#define BSz 1024
#define ROWS (Bq * Lq)          // 8192

typedef __nv_bfloat16 bf16;

// Scratch layout (floats)
#define OFF_Q     ((size_t)0)
#define OFF_K     (OFF_Q    + (size_t)ROWS * EMB)
#define OFF_V     (OFF_K    + (size_t)ROWS * EMB)
#define OFF_HHI   (OFF_V    + (size_t)ROWS * EMB)            // bf16 [8192][512]
#define OFF_HLO   (OFF_HHI  + (size_t)ROWS * EMB / 2)
#define OFF_CHI   (OFF_HLO  + (size_t)ROWS * EMB / 2)
#define OFF_CLO   (OFF_CHI  + (size_t)ROWS * EMB / 2)
#define OFF_WTHI  (OFF_CLO  + (size_t)ROWS * EMB / 2)        // bf16 [2048][512]
#define OFF_WTLO  (OFF_WTHI + (size_t)2048 * 512 / 2)
#define OFF_BIAS  (OFF_WTLO + (size_t)2048 * 512 / 2)
#define OFF_QH    (OFF_BIAS + 2048)                          // fp16 [8192][512]
#define OFF_QL    (OFF_QH   + (size_t)ROWS * EMB / 2)
#define OFF_KH    (OFF_QL   + (size_t)ROWS * EMB / 2)        // fp16, pre-scaled 1/8
#define OFF_ERH   (OFF_KH   + (size_t)ROWS * EMB / 2)        // fp16 [8][1024][64]
#define OFF_VTH   (OFF_ERH  + (size_t)Hh * BSz * HD / 2)     // fp16 [64][64][1024]
#define SCRATCH_FLOATS (OFF_VTH + (size_t)64 * HD * Lq / 2)

__device__ float g_scratch[SCRATCH_FLOATS];

// ---------------------------------------------------------------------------
// PTX helpers
// ---------------------------------------------------------------------------
__device__ __forceinline__ uint32_t smem_u32(const void* p) {
    uint32_t a;
    asm("{ .reg .u64 t; cvta.to.shared.u64 t, %1; cvt.u32.u64 %0, t; }"
        : "=r"(a) : "l"(p));
    return a;
}

#define CP_ASYNC16(saddr, gptr) \
    asm volatile("cp.async.cg.shared.global [%0], [%1], 16;" \
                 :: "r"(saddr), "l"(gptr) : "memory")
#define CP_COMMIT() asm volatile("cp.async.commit_group;" ::: "memory")
#define CP_WAIT1()  asm volatile("cp.async.wait_group 1;" ::: "memory")
#define CP_WAIT0()  asm volatile("cp.async.wait_group 0;" ::: "memory")

#define LDSM4(r0, r1, r2, r3, addr) \
    asm volatile("ldmatrix.sync.aligned.m8n8.x4.shared.b16 {%0,%1,%2,%3}, [%4];" \
                 : "=r"(r0), "=r"(r1), "=r"(r2), "=r"(r3) : "r"(addr))

#define LDSM2(r0, r1, addr) \
    asm volatile("ldmatrix.sync.aligned.m8n8.x2.shared.b16 {%0,%1}, [%2];" \
                 : "=r"(r0), "=r"(r1) : "r"(addr))

#define MMA16816(c, a0, a1, a2, a3, b0, b1) \
    asm volatile("mma.sync.aligned.m16n8k16.row.col.f32.bf16.bf16.f32 " \
                 "{%0,%1,%2,%3}, {%4,%5,%6,%7}, {%8,%9}, {%0,%1,%2,%3};" \
                 : "+f"((c)[0]), "+f"((c)[1]), "+f"((c)[2]), "+f"((c)[3]) \
                 : "r"(a0), "r"(a1), "r"(a2), "r"(a3), "r"(b0), "r"(b1))

#define MMAH(c, a, b0, b1) \
    asm volatile("mma.sync.aligned.m16n8k16.row.col.f32.f16.f16.f32 " \
                 "{%0,%1,%2,%3}, {%4,%5,%6,%7}, {%8,%9}, {%0,%1,%2,%3};" \
                 : "+f"((c)[0]), "+f"((c)[1]), "+f"((c)[2]), "+f"((c)[3]) \
                 : "r"((a)[0]), "r"((a)[1]), "r"((a)[2]), "r"((a)[3]), \
                   "r"(b0), "r"(b1))

// ---------------------------------------------------------------------------
// LayerNorm -> bf16 hi/lo split outputs
// ---------------------------------------------------------------------------
__global__ void ln_kernel(const float* __restrict__ x,
                          const float* __restrict__ gamma,
                          const float* __restrict__ beta,
                          bf16* __restrict__ hhi,
                          bf16* __restrict__ hlo)
{
    __shared__ float wsum[4], wsq[4];
    int row = blockIdx.x;
    int tid = threadIdx.x;
    const float4 v = *(const float4*)(x + (size_t)row * EMB + tid * 4);

    float s  = v.x + v.y + v.z + v.w;
    float sq = v.x * v.x + v.y * v.y + v.z * v.z + v.w * v.w;
    #pragma unroll
    for (int off = 16; off > 0; off >>= 1) {
        s  += __shfl_xor_sync(0xffffffffu, s,  off);
        sq += __shfl_xor_sync(0xffffffffu, sq, off);
    }
    int warp = tid >> 5;
    if ((tid & 31) == 0) { wsum[warp] = s; wsq[warp] = sq; }
    __syncthreads();
    float S  = wsum[0] + wsum[1] + wsum[2] + wsum[3];
    float SQ = wsq[0] + wsq[1] + wsq[2] + wsq[3];

    float mu  = S * (1.0f / EMB);
    float var = SQ * (1.0f / EMB) - mu * mu;
    float rinv = rsqrtf(var + 1e-5f);

    int c = tid * 4;
    float o[4];
    o[0] = (v.x - mu) * rinv * gamma[c + 0] + beta[c + 0];
    o[1] = (v.y - mu) * rinv * gamma[c + 1] + beta[c + 1];
    o[2] = (v.z - mu) * rinv * gamma[c + 2] + beta[c + 2];
    o[3] = (v.w - mu) * rinv * gamma[c + 3] + beta[c + 3];

    __nv_bfloat162 hp[2], lp[2];
    #pragma unroll
    for (int i = 0; i < 2; i++) {
        bf16 h0 = __float2bfloat16(o[2 * i]);
        bf16 h1 = __float2bfloat16(o[2 * i + 1]);
        bf16 l0 = __float2bfloat16(o[2 * i]     - __bfloat162float(h0));
        bf16 l1 = __float2bfloat16(o[2 * i + 1] - __bfloat162float(h1));
        hp[i].x = h0; hp[i].y = h1;
        lp[i].x = l0; lp[i].y = l1;
    }
    size_t base = (size_t)row * EMB + c;
    *(__nv_bfloat162*)(hhi + base)     = hp[0];
    *(__nv_bfloat162*)(hhi + base + 2) = hp[1];
    *(__nv_bfloat162*)(hlo + base)     = lp[0];
    *(__nv_bfloat162*)(hlo + base + 2) = lp[1];
}

// ---------------------------------------------------------------------------
// Weight transpose + bf16 split
// ---------------------------------------------------------------------------
__global__ void wt_convert_kernel(const float* __restrict__ Wq,
                                  const float* __restrict__ Wk,
                                  const float* __restrict__ Wv,
                                  const float* __restrict__ Wo,
                                  bf16* __restrict__ wthi,
                                  bf16* __restrict__ wtlo)
{
    __shared__ float t[32][33];
    int z  = blockIdx.z;
    const float* W = (z == 0) ? Wq : (z == 1) ? Wk : (z == 2) ? Wv : Wo;
    int n0 = blockIdx.x * 32;
    int k0 = blockIdx.y * 32;
    int tx = threadIdx.x, ty = threadIdx.y;

    for (int r = ty; r < 32; r += 8)
        t[r][tx] = W[(size_t)(k0 + r) * EMB + n0 + tx];
    __syncthreads();
    for (int r = ty; r < 32; r += 8) {
        float val = t[tx][r];
        bf16 h = __float2bfloat16(val);
        bf16 l = __float2bfloat16(val - __bfloat162float(h));
        size_t idx = (size_t)(z * 512 + n0 + r) * EMB + k0 + tx;
        wthi[idx] = h;
        wtlo[idx] = l;
    }
}

__global__ void bias_gather_kernel(const float* __restrict__ bq,
                                   const float* __restrict__ bk,
                                   const float* __restrict__ bv,
                                   const float* __restrict__ bo,
                                   float* __restrict__ out)
{
    int i = blockIdx.x * 256 + threadIdx.x;
    if (i >= 2048) return;
    int sel = i >> 9;
    const float* b = (sel == 0) ? bq : (sel == 1) ? bk : (sel == 2) ? bv : bo;
    out[i] = b[i & 511];
}

// ---------------------------------------------------------------------------
// q -> fp16 hi/lo ; k -> fp16 single, pre-scaled by 1/8
// ---------------------------------------------------------------------------
__global__ void qk_convert_kernel(const float* __restrict__ q,
                                  const float* __restrict__ k,
                                  __half* __restrict__ qh,
                                  __half* __restrict__ ql,
                                  __half* __restrict__ kh)
{
    size_t i = ((size_t)blockIdx.x * 256 + threadIdx.x) * 4;
    float4 qv = *(const float4*)(q + i);
    __half h0 = __float2half_rn(qv.x), h1 = __float2half_rn(qv.y);
    __half h2 = __float2half_rn(qv.z), h3 = __float2half_rn(qv.w);
    __half l0 = __float2half_rn(qv.x - __half2float(h0));
    __half l1 = __float2half_rn(qv.y - __half2float(h1));
    __half l2 = __float2half_rn(qv.z - __half2float(h2));
    __half l3 = __float2half_rn(qv.w - __half2float(h3));
    __half2 ph0 = __halves2half2(h0, h1), ph1 = __halves2half2(h2, h3);
    __half2 pl0 = __halves2half2(l0, l1), pl1 = __halves2half2(l2, l3);
    *(uint2*)(qh + i) = make_uint2(*(uint32_t*)&ph0, *(uint32_t*)&ph1);
    *(uint2*)(ql + i) = make_uint2(*(uint32_t*)&pl0, *(uint32_t*)&pl1);

    float4 kv = *(const float4*)(k + i);
    __half2 pk0 = __halves2half2(__float2half_rn(kv.x * 0.125f),
                                 __float2half_rn(kv.y * 0.125f));
    __half2 pk1 = __halves2half2(__float2half_rn(kv.z * 0.125f),
                                 __float2half_rn(kv.w * 0.125f));
    *(uint2*)(kh + i) = make_uint2(*(uint32_t*)&pk0, *(uint32_t*)&pk1);
}

// Er fp32 [8][1024][64] -> fp16 same layout
__global__ void er_convert_kernel(const float* __restrict__ er,
                                  __half* __restrict__ erh)
{
    size_t i = ((size_t)blockIdx.x * 256 + threadIdx.x) * 4;
    if (i >= (size_t)Hh * BSz * HD) return;
    float4 v = *(const float4*)(er + i);
    __half2 p0 = __halves2half2(__float2half_rn(v.x), __float2half_rn(v.y));
    __half2 p1 = __halves2half2(__float2half_rn(v.z), __float2half_rn(v.w));
    *(uint2*)(erh + i) = make_uint2(*(uint32_t*)&p0, *(uint32_t*)&p1);
}

// V fp32 [b][j][h*64+d] -> Vt fp16 [(b*8+h)*64 + d][j]
__global__ void vt_convert_kernel(const float* __restrict__ v,
                                  __half* __restrict__ vth)
{
    __shared__ float t[32][33];
    int z  = blockIdx.z;           // bh
    int bb = z >> 3, hh = z & 7;
    int l0 = blockIdx.x * 32;
    int d0 = blockIdx.y * 32;
    int tx = threadIdx.x, ty = threadIdx.y;

    for (int r = ty; r < 32; r += 8)
        t[r][tx] = v[((size_t)bb * Lq + l0 + r) * EMB + hh * HD + d0 + tx];
    __syncthreads();
    for (int r = ty; r < 32; r += 8)
        vth[((size_t)z * HD + d0 + r) * Lq + l0 + tx] = __float2half_rn(t[tx][r]);
}

// ---------------------------------------------------------------------------
// HMMA bf16 split GEMM (unchanged from passing round 11)
// ---------------------------------------------------------------------------
#define TILE_B   (128 * 80)
#define STG_B    (4 * TILE_B)
#define GEMM_SMEM_BYTES (2 * STG_B)

__global__ __launch_bounds__(256)
void hmma_gemm_kernel(const bf16* __restrict__ Ahi, const bf16* __restrict__ Alo,
                      const bf16* __restrict__ Bhi, const bf16* __restrict__ Blo,
                      const float* __restrict__ bias, int n0,
                      float* __restrict__ o0, float* __restrict__ o1,
                      float* __restrict__ o2, float* __restrict__ o3)
{
    extern __shared__ char smem[];
    uint32_t sbase = smem_u32(smem);

    int tid  = threadIdx.x;
    int wid  = tid >> 5;
    int lane = tid & 31;

    int m0     = blockIdx.y * 128;
    int nglob0 = n0 + blockIdx.x * 128;

    int warp_m = wid & 3;
    int warp_n = wid >> 2;

    float acc[2][8][4];
    #pragma unroll
    for (int mf = 0; mf < 2; mf++)
        #pragma unroll
        for (int nf = 0; nf < 8; nf++)
            #pragma unroll
            for (int e = 0; e < 4; e++) acc[mf][nf][e] = 0.0f;

    int cp_row0 = tid >> 2;
    int cp_cg0  = tid & 3;
    int cp_row1 = (tid + 256) >> 2;
    int cp_cg1  = (tid + 256) & 3;

    int a_row = warp_m * 32 + (lane & 15);
    int a_kg  = lane >> 4;
    int b_row = warp_n * 64 + (lane & 7) + ((lane >> 4) << 3);
    int b_kg  = (lane >> 3) & 1;

    #define ISSUE_CHUNK(c) do {                                               \
        uint32_t st_ = sbase + ((c) & 1) * STG_B;                             \
        const bf16* gA0 = Ahi + (size_t)(m0 + cp_row0) * EMB + (c) * 32 + cp_cg0 * 8; \
        const bf16* gA1 = Ahi + (size_t)(m0 + cp_row1) * EMB + (c) * 32 + cp_cg1 * 8; \
        CP_ASYNC16(st_ + 0 * TILE_B + cp_row0 * 80 + cp_cg0 * 16, gA0);       \
        CP_ASYNC16(st_ + 0 * TILE_B + cp_row1 * 80 + cp_cg1 * 16, gA1);       \
        const bf16* gL0 = Alo + (size_t)(m0 + cp_row0) * EMB + (c) * 32 + cp_cg0 * 8; \
        const bf16* gL1 = Alo + (size_t)(m0 + cp_row1) * EMB + (c) * 32 + cp_cg1 * 8; \
        CP_ASYNC16(st_ + 1 * TILE_B + cp_row0 * 80 + cp_cg0 * 16, gL0);       \
        CP_ASYNC16(st_ + 1 * TILE_B + cp_row1 * 80 + cp_cg1 * 16, gL1);       \
        const bf16* gB0 = Bhi + (size_t)(nglob0 + cp_row0) * EMB + (c) * 32 + cp_cg0 * 8; \
        const bf16* gB1 = Bhi + (size_t)(nglob0 + cp_row1) * EMB + (c) * 32 + cp_cg1 * 8; \
        CP_ASYNC16(st_ + 2 * TILE_B + cp_row0 * 80 + cp_cg0 * 16, gB0);       \
        CP_ASYNC16(st_ + 2 * TILE_B + cp_row1 * 80 + cp_cg1 * 16, gB1);       \
        const bf16* gC0 = Blo + (size_t)(nglob0 + cp_row0) * EMB + (c) * 32 + cp_cg0 * 8; \
        const bf16* gC1 = Blo + (size_t)(nglob0 + cp_row1) * EMB + (c) * 32 + cp_cg1 * 8; \
        CP_ASYNC16(st_ + 3 * TILE_B + cp_row0 * 80 + cp_cg0 * 16, gC0);       \
        CP_ASYNC16(st_ + 3 * TILE_B + cp_row1 * 80 + cp_cg1 * 16, gC1);       \
        CP_COMMIT();                                                          \
    } while (0)

    ISSUE_CHUNK(0);

    for (int c = 0; c < 16; c++) {
        if (c + 1 < 16) { ISSUE_CHUNK(c + 1); CP_WAIT1(); }
        else            { CP_WAIT0(); }
        __syncthreads();

        uint32_t st = sbase + (c & 1) * STG_B;
        #pragma unroll
        for (int s = 0; s < 2; s++) {
            uint32_t aoff = (uint32_t)(a_row * 80 + (s * 2 + a_kg) * 16);
            uint32_t boff = (uint32_t)(b_row * 80 + (s * 2 + b_kg) * 16);

            uint32_t ah[2][4];
            LDSM4(ah[0][0], ah[0][1], ah[0][2], ah[0][3], st + 0 * TILE_B + aoff);
            LDSM4(ah[1][0], ah[1][1], ah[1][2], ah[1][3], st + 0 * TILE_B + aoff + 16 * 80);

            uint32_t bh[4][4];
            #pragma unroll
            for (int p = 0; p < 4; p++)
                LDSM4(bh[p][0], bh[p][1], bh[p][2], bh[p][3],
                      st + 2 * TILE_B + boff + p * 16 * 80);

            #pragma unroll
            for (int mf = 0; mf < 2; mf++)
                #pragma unroll
                for (int nf = 0; nf < 8; nf++) {
                    int p = nf >> 1, q = (nf & 1) * 2;
                    MMA16816(acc[mf][nf], ah[mf][0], ah[mf][1], ah[mf][2], ah[mf][3],
                             bh[p][q], bh[p][q + 1]);
                }

            uint32_t al[2][4];
            LDSM4(al[0][0], al[0][1], al[0][2], al[0][3], st + 1 * TILE_B + aoff);
            LDSM4(al[1][0], al[1][1], al[1][2], al[1][3], st + 1 * TILE_B + aoff + 16 * 80);
            #pragma unroll
            for (int mf = 0; mf < 2; mf++)
                #pragma unroll
                for (int nf = 0; nf < 8; nf++) {
                    int p = nf >> 1, q = (nf & 1) * 2;
                    MMA16816(acc[mf][nf], al[mf][0], al[mf][1], al[mf][2], al[mf][3],
                             bh[p][q], bh[p][q + 1]);
                }

            #pragma unroll
            for (int p = 0; p < 4; p++)
                LDSM4(bh[p][0], bh[p][1], bh[p][2], bh[p][3],
                      st + 3 * TILE_B + boff + p * 16 * 80);
            #pragma unroll
            for (int mf = 0; mf < 2; mf++)
                #pragma unroll
                for (int nf = 0; nf < 8; nf++) {
                    int p = nf >> 1, q = (nf & 1) * 2;
                    MMA16816(acc[mf][nf], ah[mf][0], ah[mf][1], ah[mf][2], ah[mf][3],
                             bh[p][q], bh[p][q + 1]);
                }
        }
        __syncthreads();
    }

    int sel = nglob0 >> 9;
    float* outp = (sel == 0) ? o0 : (sel == 1) ? o1 : (sel == 2) ? o2 : o3;
    int ncol0 = (nglob0 & 511) + warp_n * 64;
    int g  = lane >> 2;
    int tg = lane & 3;

    #pragma unroll
    for (int mf = 0; mf < 2; mf++) {
        int r0 = m0 + warp_m * 32 + mf * 16 + g;
        #pragma unroll
        for (int nf = 0; nf < 8; nf++) {
            int col = ncol0 + nf * 8 + 2 * tg;
            int bcol = nglob0 - (nglob0 & 511) + col;
            float b0 = bias[bcol], b1 = bias[bcol + 1];
            float2 v0 = make_float2(acc[mf][nf][0] + b0, acc[mf][nf][1] + b1);
            float2 v1 = make_float2(acc[mf][nf][2] + b0, acc[mf][nf][3] + b1);
            *(float2*)(outp + (size_t)r0 * EMB + col)       = v0;
            *(float2*)(outp + (size_t)(r0 + 8) * EMB + col) = v1;
        }
    }
}

// ---------------------------------------------------------------------------
// HMMA attention. Per block: (b,h), 32 query rows, 256 threads (8 warps).
// Phase E: E[r][p] = q.Er, fragments scattered to sc at col (p+l)%1024.
// Phase S: sc[r][j] += q.k' (k pre-scaled 1/8). Softmax. Phase C: P@V.
// A operands (q, P) fp16 hi/lo 2-pass; B operands (Er, K, Vt) single fp16.
// smem bytes: sc 132608 | qs hi/lo 9216 | staging 36864  = 178688
// ---------------------------------------------------------------------------
#define SC_LD    1036
#define SC_BYTES (32 * SC_LD * 4)          // 132608
#define QSH_OFF  SC_BYTES
#define QSL_OFF  (QSH_OFF + 4608)
#define ASTG_OFF (QSL_OFF + 4608)          // 141824
#define VB_OFF   ASTG_OFF
#define PBH_OFF  (ASTG_OFF + 17408)
#define PBL_OFF  (PBH_OFF + 8704)
#define ATTN_SMEM_BYTES (ASTG_OFF + 2 * 18432)   // 178688

__global__ __launch_bounds__(256, 1)
void attn_kernel(const __half* __restrict__ qh, const __half* __restrict__ ql,
                 const __half* __restrict__ kh, const __half* __restrict__ erh,
                 const __half* __restrict__ vth,
                 bf16* __restrict__ chi, bf16* __restrict__ clo)
{
    extern __shared__ char smc[];
    float* sc = (float*)smc;
    uint32_t sbase = smem_u32(smc);

    int bh = blockIdx.y;
    int hh = bh & 7;
    int bb = bh >> 3;
    int l0 = blockIdx.x * 32;
    int tid  = threadIdx.x;
    int wid  = tid >> 5;
    int lane = tid & 31;

    // ---- stage q hi/lo into smem (stride 144B) ----
    {
        int r  = tid >> 3;
        int gg = tid & 7;
        size_t gidx = ((size_t)(bb * Lq + l0 + r)) * EMB + hh * HD + gg * 8;
        *(uint4*)(smc + QSH_OFF + r * 144 + gg * 16) = *(const uint4*)(qh + gidx);
        *(uint4*)(smc + QSL_OFF + r * 144 + gg * 16) = *(const uint4*)(ql + gidx);
    }
    __syncthreads();

    // ---- A fragments for q (held all kernel) ----
    int a_row = lane & 15;
    int a_kg  = lane >> 4;
    uint32_t qhf[2][4][4], qlf[2][4][4];
    #pragma unroll
    for (int mf = 0; mf < 2; mf++)
        #pragma unroll
        for (int kc = 0; kc < 4; kc++) {
            uint32_t off = (uint32_t)((mf * 16 + a_row) * 144 + kc * 32 + a_kg * 16);
            LDSM4(qhf[mf][kc][0], qhf[mf][kc][1], qhf[mf][kc][2], qhf[mf][kc][3],
                  sbase + QSH_OFF + off);
            LDSM4(qlf[mf][kc][0], qlf[mf][kc][1], qlf[mf][kc][2], qlf[mf][kc][3],
                  sbase + QSL_OFF + off);
        }

    int b_row = wid * 16 + (lane & 7) + ((lane >> 4) << 3);
    int b_kg  = (lane >> 3) & 1;
    int g  = lane >> 2;
    int tg = lane & 3;

    // cp.async granule map for 128x64 fp16 tiles (8 granules/row, stride 144B)
    #define ISSUE_ER(jt_) do {                                                \
        uint32_t dst = sbase + ASTG_OFF + ((jt_) & 1) * 18432;                \
        _Pragma("unroll")                                                     \
        for (int i_ = 0; i_ < 4; i_++) {                                      \
            int G = tid + i_ * 256;                                           \
            int row = G >> 3, gg_ = G & 7;                                    \
            CP_ASYNC16(dst + row * 144 + gg_ * 16,                            \
                erh + ((size_t)(hh * BSz + (jt_) * 128 + row)) * HD + gg_ * 8); \
        }                                                                     \
        CP_COMMIT();                                                          \
    } while (0)

    #define ISSUE_K(jt_) do {                                                 \
        uint32_t dst = sbase + ASTG_OFF + ((jt_) & 1) * 18432;                \
        _Pragma("unroll")                                                     \
        for (int i_ = 0; i_ < 4; i_++) {                                      \
            int G = tid + i_ * 256;                                           \
            int row = G >> 3, gg_ = G & 7;                                    \
            CP_ASYNC16(dst + row * 144 + gg_ * 16,                            \
                kh + ((size_t)(bb * Lq + (jt_) * 128 + row)) * EMB + hh * HD + gg_ * 8); \
        }                                                                     \
        CP_COMMIT();                                                          \
    } while (0)

    // ================= Phase E: QEr -> rotated scatter =================
    ISSUE_ER(0);
    for (int jt = 0; jt < 8; jt++) {
        if (jt < 7) { ISSUE_ER(jt + 1); CP_WAIT1(); } else { CP_WAIT0(); }
        __syncthreads();

        uint32_t kb = sbase + ASTG_OFF + (jt & 1) * 18432;
        uint32_t bfr[4][4];
        #pragma unroll
        for (int kc = 0; kc < 4; kc++)
            LDSM4(bfr[kc][0], bfr[kc][1], bfr[kc][2], bfr[kc][3],
                  kb + b_row * 144 + kc * 32 + b_kg * 16);

        float acc[2][2][4];
        #pragma unroll
        for (int mf = 0; mf < 2; mf++)
            #pragma unroll
            for (int nf = 0; nf < 2; nf++)
                #pragma unroll
                for (int e = 0; e < 4; e++) acc[mf][nf][e] = 0.0f;

        #pragma unroll
        for (int kc = 0; kc < 4; kc++)
            #pragma unroll
            for (int mf = 0; mf < 2; mf++)
                #pragma unroll
                for (int nf = 0; nf < 2; nf++) {
                    MMAH(acc[mf][nf], qhf[mf][kc], bfr[kc][nf * 2], bfr[kc][nf * 2 + 1]);
                    MMAH(acc[mf][nf], qlf[mf][kc], bfr[kc][nf * 2], bfr[kc][nf * 2 + 1]);
                }

        #pragma unroll
        for (int mf = 0; mf < 2; mf++)
            #pragma unroll
            for (int nf = 0; nf < 2; nf++) {
                int pcol = jt * 128 + wid * 16 + nf * 8 + 2 * tg;
                int r1 = mf * 16 + g, r2 = r1 + 8;
                sc[r1 * SC_LD + ((pcol     + l0 + r1) & 1023)] = acc[mf][nf][0];
                sc[r1 * SC_LD + ((pcol + 1 + l0 + r1) & 1023)] = acc[mf][nf][1];
                sc[r2 * SC_LD + ((pcol     + l0 + r2) & 1023)] = acc[mf][nf][2];
                sc[r2 * SC_LD + ((pcol + 1 + l0 + r2) & 1023)] = acc[mf][nf][3];
            }
        __syncthreads();
    }

    // ================= Phase S: scores accumulate =================
    ISSUE_K(0);
    for (int jt = 0; jt < 8; jt++) {
        if (jt < 7) { ISSUE_K(jt + 1); CP_WAIT1(); } else { CP_WAIT0(); }
        __syncthreads();

        uint32_t kb = sbase + ASTG_OFF + (jt & 1) * 18432;
        uint32_t bfr[4][4];
        #pragma unroll
        for (int kc = 0; kc < 4; kc++)
            LDSM4(bfr[kc][0], bfr[kc][1], bfr[kc][2], bfr[kc][3],
                  kb + b_row * 144 + kc * 32 + b_kg * 16);

        float acc[2][2][4];
        #pragma unroll
        for (int mf = 0; mf < 2; mf++)
            #pragma unroll
            for (int nf = 0; nf < 2; nf++)
                #pragma unroll
                for (int e = 0; e < 4; e++) acc[mf][nf][e] = 0.0f;

        #pragma unroll
        for (int kc = 0; kc < 4; kc++)
            #pragma unroll
            for (int mf = 0; mf < 2; mf++)
                #pragma unroll
                for (int nf = 0; nf < 2; nf++) {
                    MMAH(acc[mf][nf], qhf[mf][kc], bfr[kc][nf * 2], bfr[kc][nf * 2 + 1]);
                    MMAH(acc[mf][nf], qlf[mf][kc], bfr[kc][nf * 2], bfr[kc][nf * 2 + 1]);
                }

        #pragma unroll
        for (int mf = 0; mf < 2; mf++)
            #pragma unroll
            for (int nf = 0; nf < 2; nf++) {
                int col = jt * 128 + wid * 16 + nf * 8 + 2 * tg;
                int r1 = mf * 16 + g, r2 = r1 + 8;
                sc[r1 * SC_LD + col]     += acc[mf][nf][0];
                sc[r1 * SC_LD + col + 1] += acc[mf][nf][1];
                sc[r2 * SC_LD + col]     += acc[mf][nf][2];
                sc[r2 * SC_LD + col + 1] += acc[mf][nf][3];
            }
        __syncthreads();
    }

    // ================= Softmax =================
    {
        int row = wid * 4 + (lane >> 3);
        int sub = lane & 7;
        float* srow = sc + row * SC_LD;

        float m = -1e30f;
        for (int t = 0; t < 128; t++)
            m = fmaxf(m, srow[sub + t * 8]);
        #pragma unroll
        for (int off = 4; off > 0; off >>= 1)
            m = fmaxf(m, __shfl_xor_sync(0xffffffffu, m, off));

        float ssum = 0.0f;
        for (int t = 0; t < 128; t++) {
            float e = __expf(srow[sub + t * 8] - m);
            srow[sub + t * 8] = e;
            ssum += e;
        }
        #pragma unroll
        for (int off = 4; off > 0; off >>= 1)
            ssum += __shfl_xor_sync(0xffffffffu, ssum, off);

        float inv = 1.0f / ssum;
        for (int t = 0; t < 128; t++)
            srow[sub + t * 8] *= inv;
    }
    __syncthreads();

    // ================= Phase C: out = P @ V (fp16 2-pass) =================
    float oacc[2][4];
    #pragma unroll
    for (int mf = 0; mf < 2; mf++)
        #pragma unroll
        for (int e = 0; e < 4; e++) oacc[mf][e] = 0.0f;

    for (int kt = 0; kt < 8; kt++) {
        // stage Vt tile [64 d][128 j], stride 272B
        {
            #pragma unroll
            for (int i_ = 0; i_ < 4; i_++) {
                int G = tid + i_ * 256;
                int row = G >> 4, gg_ = G & 15;
                CP_ASYNC16(sbase + VB_OFF + row * 272 + gg_ * 16,
                    vth + ((size_t)(bh * HD + row)) * Lq + kt * 128 + gg_ * 8);
            }
            CP_COMMIT();
        }
        // convert P tile -> fp16 hi/lo while cp.async in flight
        {
            int r = tid >> 3, seg = tid & 7;
            const float* srow = sc + r * SC_LD + kt * 128 + seg * 16;
            uint32_t hw[8], lw[8];
            #pragma unroll
            for (int u = 0; u < 8; u++) {
                float2 v = *(const float2*)(srow + u * 2);
                __half a  = __float2half_rn(v.x);
                __half b  = __float2half_rn(v.y);
                __half al = __float2half_rn(v.x - __half2float(a));
                __half bl = __float2half_rn(v.y - __half2float(b));
                __half2 ph = __halves2half2(a, b);
                __half2 pl = __halves2half2(al, bl);
                hw[u] = *(uint32_t*)&ph;
                lw[u] = *(uint32_t*)&pl;
            }
            *(uint4*)(smc + PBH_OFF + r * 272 + seg * 32)      = make_uint4(hw[0], hw[1], hw[2], hw[3]);
            *(uint4*)(smc + PBH_OFF + r * 272 + seg * 32 + 16) = make_uint4(hw[4], hw[5], hw[6], hw[7]);
            *(uint4*)(smc + PBL_OFF + r * 272 + seg * 32)      = make_uint4(lw[0], lw[1], lw[2], lw[3]);
            *(uint4*)(smc + PBL_OFF + r * 272 + seg * 32 + 16) = make_uint4(lw[4], lw[5], lw[6], lw[7]);
        }
        CP_WAIT0();
        __syncthreads();

        #pragma unroll
        for (int kc = 0; kc < 8; kc++) {
            uint32_t bv0, bv1;
            LDSM2(bv0, bv1, sbase + VB_OFF + (wid * 8 + (lane & 7)) * 272
                             + kc * 32 + ((lane >> 3) & 1) * 16);
            #pragma unroll
            for (int mf = 0; mf < 2; mf++) {
                uint32_t pf[4];
                uint32_t aoff = (uint32_t)((mf * 16 + a_row) * 272 + kc * 32 + a_kg * 16);
                LDSM4(pf[0], pf[1], pf[2], pf[3], sbase + PBH_OFF + aoff);
                MMAH(oacc[mf], pf, bv0, bv1);
                LDSM4(pf[0], pf[1], pf[2], pf[3], sbase + PBL_OFF + aoff);
                MMAH(oacc[mf], pf, bv0, bv1);
            }
        }
        __syncthreads();
    }

    // epilogue: ctx hi/lo bf16
    #pragma unroll
    for (int mf = 0; mf < 2; mf++) {
        int col = wid * 8 + 2 * tg;
        #pragma unroll
        for (int h2 = 0; h2 < 2; h2++) {
            int r = mf * 16 + g + h2 * 8;
            float v0 = oacc[mf][h2 * 2 + 0];
            float v1 = oacc[mf][h2 * 2 + 1];
            bf16 x0 = __float2bfloat16(v0);
            bf16 x1 = __float2bfloat16(v1);
            bf16 y0 = __float2bfloat16(v0 - __bfloat162float(x0));
            bf16 y1 = __float2bfloat16(v1 - __bfloat162float(x1));
            __nv_bfloat162 hp; hp.x = x0; hp.y = x1;
            __nv_bfloat162 lp; lp.x = y0; lp.y = y1;
            size_t base = ((size_t)(bb * Lq + l0 + r)) * EMB + hh * HD + col;
            *(__nv_bfloat162*)(chi + base) = hp;
            *(__nv_bfloat162*)(clo + base) = lp;
        }
    }
}

// ---------------------------------------------------------------------------
extern "C" void kernel_launch(void* const* d_in, const int* in_sizes, int n_in,
                              void* d_out, int out_size)
{
    const float* x    = (const float*)d_in[0];
    const float* ln_g = (const float*)d_in[1];
    const float* ln_b = (const float*)d_in[2];
    const float* Wq   = (const float*)d_in[3];
    const float* bq   = (const float*)d_in[4];
    const float* Wk   = (const float*)d_in[5];
    const float* bk   = (const float*)d_in[6];
    const float* Wv   = (const float*)d_in[7];
    const float* bv   = (const float*)d_in[8];
    const float* Wo   = (const float*)d_in[9];
    const float* bo   = (const float*)d_in[10];
    const float* Er   = (const float*)d_in[11];
    float* out = (float*)d_out;

    float* scr = nullptr;
    cudaGetSymbolAddress((void**)&scr, g_scratch);
    float*  g_q    = scr + OFF_Q;
    float*  g_k    = scr + OFF_K;
    float*  g_v    = scr + OFF_V;
    bf16*   g_hhi  = (bf16*)(scr + OFF_HHI);
    bf16*   g_hlo  = (bf16*)(scr + OFF_HLO);
    bf16*   g_chi  = (bf16*)(scr + OFF_CHI);
    bf16*   g_clo  = (bf16*)(scr + OFF_CLO);
    bf16*   g_wthi = (bf16*)(scr + OFF_WTHI);
    bf16*   g_wtlo = (bf16*)(scr + OFF_WTLO);
    float*  g_bias = scr + OFF_BIAS;
    __half* g_qh   = (__half*)(scr + OFF_QH);
    __half* g_ql   = (__half*)(scr + OFF_QL);
    __half* g_kh   = (__half*)(scr + OFF_KH);
    __half* g_erh  = (__half*)(scr + OFF_ERH);
    __half* g_vth  = (__half*)(scr + OFF_VTH);

    static bool attr_set = false;
    if (!attr_set) {
        cudaFuncSetAttribute(attn_kernel, cudaFuncAttributeMaxDynamicSharedMemorySize,
                             ATTN_SMEM_BYTES);
        cudaFuncSetAttribute(hmma_gemm_kernel, cudaFuncAttributeMaxDynamicSharedMemorySize,
                             GEMM_SMEM_BYTES);
        attr_set = true;
    }

    // 1. LayerNorm -> h hi/lo (bf16)
    ln_kernel<<<ROWS, 128>>>(x, ln_g, ln_b, g_hhi, g_hlo);

    // 2. Weight transpose+split, bias gather, Er -> fp16
    wt_convert_kernel<<<dim3(16, 16, 4), dim3(32, 8)>>>(Wq, Wk, Wv, Wo, g_wthi, g_wtlo);
    bias_gather_kernel<<<8, 256>>>(bq, bk, bv, bo, g_bias);
    er_convert_kernel<<<512, 256>>>(Er, g_erh);

    // 3. QKV projection: HMMA GEMM, N = 1536 -> q,k,v fp32
    hmma_gemm_kernel<<<dim3(12, 64), 256, GEMM_SMEM_BYTES>>>(
        g_hhi, g_hlo, g_wthi, g_wtlo, g_bias, 0, g_q, g_k, g_v, out);

    // 4. fp16 conversions for attention operands
    qk_convert_kernel<<<4096, 256>>>(g_q, g_k, g_qh, g_ql, g_kh);
    vt_convert_kernel<<<dim3(Lq / 32, HD / 32, Bq * Hh), dim3(32, 8)>>>(g_v, g_vth);

    // 5. HMMA attention -> ctx hi/lo (bf16)
    attn_kernel<<<dim3(Lq / 32, Bq * Hh), 256, ATTN_SMEM_BYTES>>>(
        g_qh, g_ql, g_kh, g_erh, g_vth, g_chi, g_clo);

    // 6. O projection: HMMA GEMM, N in [1536, 2048) -> d_out
    hmma_gemm_kernel<<<dim3(4, 64), 256, GEMM_SMEM_BYTES>>>(
        g_chi, g_clo, g_wthi, g_wtlo, g_bias, 1536, g_q, g_k, g_v, out);
}